// round 14
// baseline (speedup 1.0000x reference)
#include <cuda_runtime.h>
#include <cuda_fp16.h>
#include <math.h>
#include <stdint.h>

#define NTOK 32768
#define HID  1024
#define NS   64
#define KTOT 3072
#define LPAD 128
#define TAU1 3e-3f
#define TAU2 2e-5f

// ------------------------- device scratch ---------------------------------
__device__ float g_h [(size_t)NTOK * HID];
__device__ float g_hd[(size_t)NTOK * (HID / 2)];
__device__ float g_hrep [(size_t)NTOK * HID];
__device__ float g_hrep2[(size_t)NTOK * HID];
__device__ float g_logits[(size_t)NTOK * LPAD];
__device__ __half g_h16[(size_t)NTOK * HID];
__device__ __half g_xh[(size_t)NTOK * KTOT];
__device__ __half g_xl[(size_t)NTOK * KTOT];
__device__ __half g_w1a[(size_t)HID * KTOT];
__device__ __half g_w1b[(size_t)HID * KTOT];
__device__ __half g_wd[(size_t)(HID / 2) * KTOT];
__device__ __half g_w2h[(size_t)LPAD * HID];
__device__ float  g_b2p[LPAD];
__device__ int g_nflag;
__device__ int g_flagidx[NTOK];
__device__ int g_nflag2;
__device__ int g_flagidx2[NTOK];

__device__ __forceinline__ float gelu_exact(float x) {
    return 0.5f * x * (1.0f + erff(x * 0.70710678118654752440f));
}
__device__ __forceinline__ void cp16(uint32_t d, const void* s) {
    asm volatile("cp.async.cg.shared.global [%0], [%1], 16;" :: "r"(d), "l"(s));
}
#define CP_COMMIT() asm volatile("cp.async.commit_group;" ::: "memory")
#define CP_WAIT1()  asm volatile("cp.async.wait_group 1;" ::: "memory")
#define CP_WAIT2()  asm volatile("cp.async.wait_group 2;" ::: "memory")
__device__ __forceinline__ void mma16h(float* c, const uint32_t* a, const uint32_t* b) {
    asm volatile("mma.sync.aligned.m16n8k16.row.col.f32.f16.f16.f32 "
        "{%0,%1,%2,%3}, {%4,%5,%6,%7}, {%8,%9}, {%0,%1,%2,%3};"
        : "+f"(c[0]), "+f"(c[1]), "+f"(c[2]), "+f"(c[3])
        : "r"(a[0]), "r"(a[1]), "r"(a[2]), "r"(a[3]), "r"(b[0]), "r"(b[1]));
}
__device__ __forceinline__ void ldsm4(uint32_t& r0, uint32_t& r1, uint32_t& r2,
                                      uint32_t& r3, uint32_t addr) {
    asm volatile("ldmatrix.sync.aligned.m8n8.x4.shared.b16 {%0,%1,%2,%3}, [%4];"
                 : "=r"(r0), "=r"(r1), "=r"(r2), "=r"(r3) : "r"(addr));
}

// ---------------------- prep kernels --------------------------------------
__device__ __forceinline__ void hsplit2(float x, uint16_t& s1, uint16_t& s2) {
    __half h1 = __float2half_rn(x);
    __half h2 = __float2half_rn(x - __half2float(h1));
    s1 = __half_as_ushort(h1);
    s2 = __half_as_ushort(h2);
}

__global__ __launch_bounds__(256)
void splitX2h(const float* __restrict__ in, __half* __restrict__ oa,
              __half* __restrict__ ob, int col0)
{
    const int idx4 = blockIdx.x * 256 + threadIdx.x;
    if (idx4 >= NTOK * HID / 4) return;
    const int n = idx4 >> 8, c4 = idx4 & 255;
    float4 v = reinterpret_cast<const float4*>(in)[idx4];
    uint16_t a[4], b[4];
    hsplit2(v.x, a[0], b[0]); hsplit2(v.y, a[1], b[1]);
    hsplit2(v.z, a[2], b[2]); hsplit2(v.w, a[3], b[3]);
    const size_t off = (size_t)n * KTOT + col0 + c4 * 4;
    *reinterpret_cast<uint2*>(oa + off) =
        make_uint2((uint32_t)a[0] | ((uint32_t)a[1] << 16),
                   (uint32_t)a[2] | ((uint32_t)a[3] << 16));
    *reinterpret_cast<uint2*>(ob + off) =
        make_uint2((uint32_t)b[0] | ((uint32_t)b[1] << 16),
                   (uint32_t)b[2] | ((uint32_t)b[3] << 16));
}

__global__ __launch_bounds__(256)
void splitW2h(const float* __restrict__ in, __half* __restrict__ oa,
              __half* __restrict__ ob, int n4)
{
    const int idx4 = blockIdx.x * 256 + threadIdx.x;
    if (idx4 >= n4) return;
    float4 v = reinterpret_cast<const float4*>(in)[idx4];
    uint16_t a[4], b[4];
    hsplit2(v.x, a[0], b[0]); hsplit2(v.y, a[1], b[1]);
    hsplit2(v.z, a[2], b[2]); hsplit2(v.w, a[3], b[3]);
    const size_t off = (size_t)idx4 * 4;
    *reinterpret_cast<uint2*>(oa + off) =
        make_uint2((uint32_t)a[0] | ((uint32_t)a[1] << 16),
                   (uint32_t)a[2] | ((uint32_t)a[3] << 16));
    *reinterpret_cast<uint2*>(ob + off) =
        make_uint2((uint32_t)b[0] | ((uint32_t)b[1] << 16),
                   (uint32_t)b[2] | ((uint32_t)b[3] << 16));
}

__global__ __launch_bounds__(256)
void convWh(const float* __restrict__ in, __half* __restrict__ oa, int n4)
{
    const int idx4 = blockIdx.x * 256 + threadIdx.x;
    if (idx4 >= n4) return;
    float4 v = reinterpret_cast<const float4*>(in)[idx4];
    uint16_t a0 = __half_as_ushort(__float2half_rn(v.x));
    uint16_t a1 = __half_as_ushort(__float2half_rn(v.y));
    uint16_t a2 = __half_as_ushort(__float2half_rn(v.z));
    uint16_t a3 = __half_as_ushort(__float2half_rn(v.w));
    *reinterpret_cast<uint2*>(oa + (size_t)idx4 * 4) =
        make_uint2((uint32_t)a0 | ((uint32_t)a1 << 16),
                   (uint32_t)a2 | ((uint32_t)a3 << 16));
}

__global__ __launch_bounds__(256)
void prepW2(const float* __restrict__ W2, const float* __restrict__ b2,
            __half* __restrict__ w2h, float* __restrict__ b2p)
{
    const int idx = blockIdx.x * 256 + threadIdx.x;
    if (idx < LPAD * HID) {
        const int row = idx >> 10;
        float v = (row < NS) ? W2[(size_t)row * HID + (idx & 1023)] : 0.0f;
        w2h[idx] = __float2half_rn(v);
    }
    if (idx < LPAD) b2p[idx] = (idx < NS) ? b2[idx] : 0.0f;
}

// ---- BIG-TILE fp16 1-term mma GEMM: CTA 256x128, warp tile 64x64 ---------
#define RSW   20
#define LVLW  (128 * RSW)          // legacy level size (tier-1 kernel)
#define NITER (KTOT / 32)
#define NSTAGE 3
#define BG_AW  (256 * RSW)                 // A region words per stage
#define BG_SW  (BG_AW + 128 * RSW)         // stage words (A 256 rows + B 128 rows)
#define SMEM_BIG_BYTES (NSTAGE * BG_SW * 4)   // 92160

static __device__ __forceinline__ void fill_big(
    const __half* __restrict__ xh, const __half* __restrict__ w,
    int m0, int n0, int k0, int tid, int stage, uint32_t sbase, int kstride)
{
    #pragma unroll
    for (int p = 0; p < 6; p++) {
        const int c = tid + p * 256;             // 0..1535
        const bool isA = (c < 1024);
        const int cc   = isA ? c : c - 1024;
        const int row  = cc >> 2;
        const int q    = cc & 3;
        const __half* src = isA
            ? xh + (size_t)(m0 + row) * kstride + k0 + q * 8
            : w  + (size_t)(n0 + row) * kstride + k0 + q * 8;
        const uint32_t dw = (uint32_t)(stage * BG_SW + (isA ? 0 : BG_AW)
                                       + row * RSW + q * 4);
        cp16(sbase + dw * 4u, src);
    }
}

template<int KDIM, bool DOGELU, bool WH16>
__global__ void __launch_bounds__(256)
gemm_big(const __half* __restrict__ xh,
         const __half* __restrict__ w1, const __half* __restrict__ wd,
         const float* __restrict__ b1, const float* __restrict__ bd,
         float* __restrict__ out1, float* __restrict__ outd,
         __half* __restrict__ h16, int nblk1, int nout1, int nout2)
{
    extern __shared__ uint32_t smw[];
    const int bx = blockIdx.x;
    const bool first = (bx < nblk1);
    const __half* w    = first ? w1 : wd;
    const float* bias  = first ? b1 : bd;
    float* out         = first ? out1 : outd;
    const int Nout     = first ? nout1 : nout2;
    const int n0       = (first ? bx : bx - nblk1) * 128;

    const int tid  = threadIdx.x;
    const int lane = tid & 31;
    const int wid  = tid >> 5;
    const int g    = lane >> 2;
    const int t    = lane & 3;
    const int warp_m = wid >> 1;         // 0..3 (64 rows each)
    const int warp_n = wid & 1;          // 0..1 (64 cols each)
    const int m0 = blockIdx.y * 256;
    const uint32_t sbase = (uint32_t)__cvta_generic_to_shared(smw);

    const int la_row  = (lane & 7) + ((lane >> 3) & 1) * 8;
    const int la_colw = ((lane >> 4) & 1) * 4;
    const int lb_row  = (lane & 7) + ((lane >> 4) & 1) * 8;
    const int lb_colw = ((lane >> 3) & 1) * 4;
    const uint32_t aw0 = (uint32_t)((warp_m * 64 + la_row) * RSW + la_colw);
    const uint32_t bw0 = (uint32_t)(BG_AW + (warp_n * 64 + lb_row) * RSW + lb_colw);

    float acc[4][8][4];
    #pragma unroll
    for (int mi = 0; mi < 4; mi++)
        #pragma unroll
        for (int ni = 0; ni < 8; ni++)
            #pragma unroll
            for (int q = 0; q < 4; q++) acc[mi][ni][q] = 0.0f;

    const int niter = KDIM / 32;
    fill_big(xh, w, m0, n0, 0,  tid, 0, sbase, KDIM); CP_COMMIT();
    fill_big(xh, w, m0, n0, 32, tid, 1, sbase, KDIM); CP_COMMIT();
    fill_big(xh, w, m0, n0, 64, tid, 2, sbase, KDIM); CP_COMMIT();

    int stage = 0;
    #pragma unroll 1
    for (int iter = 0; iter < niter; iter++) {
        CP_WAIT2();
        __syncthreads();
        const uint32_t sstage = sbase + (uint32_t)(stage * BG_SW) * 4u;

        #pragma unroll
        for (int kc = 0; kc < 2; kc++) {
            uint32_t af[4][4];
            #pragma unroll
            for (int mi = 0; mi < 4; mi++)
                ldsm4(af[mi][0], af[mi][1], af[mi][2], af[mi][3],
                      sstage + (aw0 + (uint32_t)(mi * 16 * RSW + kc * 8)) * 4u);

            uint32_t bf_[8][2];
            #pragma unroll
            for (int p = 0; p < 4; p++) {
                uint32_t r0, r1, r2, r3;
                ldsm4(r0, r1, r2, r3,
                      sstage + (bw0 + (uint32_t)(p * 16 * RSW + kc * 8)) * 4u);
                bf_[2 * p][0]     = r0;  bf_[2 * p][1]     = r1;
                bf_[2 * p + 1][0] = r2;  bf_[2 * p + 1][1] = r3;
            }

            #pragma unroll
            for (int mi = 0; mi < 4; mi++)
                #pragma unroll
                for (int ni = 0; ni < 8; ni++)
                    mma16h(acc[mi][ni], af[mi], bf_[ni]);
        }
        __syncthreads();
        if (iter + NSTAGE < niter)
            fill_big(xh, w, m0, n0, (iter + NSTAGE) * 32, tid, stage, sbase, KDIM);
        CP_COMMIT();
        stage = (stage == NSTAGE - 1) ? 0 : stage + 1;
    }

    #pragma unroll
    for (int mi = 0; mi < 4; mi++)
        #pragma unroll
        for (int half = 0; half < 2; half++) {
            const int row = m0 + warp_m * 64 + mi * 16 + g + half * 8;
            #pragma unroll
            for (int ni = 0; ni < 8; ni++) {
                const int col = n0 + warp_n * 64 + ni * 8 + 2 * t;
                float2 b = *(const float2*)(bias + col);
                float2 r;
                if (DOGELU) {
                    r.x = gelu_exact(acc[mi][ni][half * 2 + 0] + b.x);
                    r.y = gelu_exact(acc[mi][ni][half * 2 + 1] + b.y);
                } else {
                    r.x = acc[mi][ni][half * 2 + 0] + b.x;
                    r.y = acc[mi][ni][half * 2 + 1] + b.y;
                }
                *(float2*)(out + (size_t)row * Nout + col) = r;
                if (WH16 && first)
                    *(__half2*)(h16 + (size_t)row * HID + col) =
                        __floats2half2_rn(r.x, r.y);
            }
        }
}

// ---- TIER-1 repair: gathered 3-term fp16 mma GEMM (proven R12 kernel) ----
#define T1_SWORDS (4 * LVLW)
#define T1_SMEM_BYTES (2 * T1_SWORDS * 4)   // 81920

static __device__ __forceinline__ void fill_t1(
    const __half* __restrict__ xa, const __half* __restrict__ xb,
    const __half* __restrict__ wa, const __half* __restrict__ wb,
    const int* sidx, int n0, int k0, int tid, int stage, uint32_t sbase)
{
    const __half* srcs[4] = {xa, xb, wa, wb};
    #pragma unroll
    for (int p = 0; p < 8; p++) {
        const int slot = p >> 1;
        const int c    = tid + (p & 1) * 256;
        const int row  = c >> 2;
        const int q    = c & 3;
        const __half* src = (slot < 2)
            ? srcs[slot] + (size_t)sidx[row] * KTOT + k0 + q * 8
            : srcs[slot] + (size_t)(n0 + row) * KTOT + k0 + q * 8;
        const uint32_t dw = (uint32_t)(stage * T1_SWORDS + slot * LVLW + row * RSW + q * 4);
        cp16(sbase + dw * 4u, src);
    }
}

__global__ void __launch_bounds__(256)
gemm_t1_f16x3(const __half* __restrict__ xa, const __half* __restrict__ xb,
              const __half* __restrict__ wa, const __half* __restrict__ wb,
              const float* __restrict__ bias, float* __restrict__ out)
{
    const int nflag = g_nflag;
    const int m0 = blockIdx.y * 128;
    if (m0 >= nflag) return;
    extern __shared__ uint32_t smw[];
    __shared__ int sidx[128];

    const int tid  = threadIdx.x;
    const int lane = tid & 31;
    const int wid  = tid >> 5;
    const int g    = lane >> 2;
    const int t    = lane & 3;
    const int warp_m = wid >> 1;
    const int warp_n = wid & 1;
    const int n0 = blockIdx.x * 128;
    const uint32_t sbase = (uint32_t)__cvta_generic_to_shared(smw);

    if (tid < 128)
        sidx[tid] = g_flagidx[(m0 + tid < nflag) ? m0 + tid : 0];
    __syncthreads();

    const int la_row  = (lane & 7) + ((lane >> 3) & 1) * 8;
    const int la_colw = ((lane >> 4) & 1) * 4;
    const int lb_row  = (lane & 7) + ((lane >> 4) & 1) * 8;
    const int lb_colw = ((lane >> 3) & 1) * 4;
    const uint32_t aw0 = (uint32_t)((warp_m * 32 + la_row) * RSW + la_colw);
    const uint32_t bw0 = (uint32_t)(2 * LVLW + (warp_n * 64 + lb_row) * RSW + lb_colw);

    float acc[2][8][4];
    #pragma unroll
    for (int mi = 0; mi < 2; mi++)
        #pragma unroll
        for (int ni = 0; ni < 8; ni++)
            #pragma unroll
            for (int q = 0; q < 4; q++) acc[mi][ni][q] = 0.0f;

    fill_t1(xa, xb, wa, wb, sidx, n0, 0,  tid, 0, sbase); CP_COMMIT();
    fill_t1(xa, xb, wa, wb, sidx, n0, 32, tid, 1, sbase); CP_COMMIT();

    #pragma unroll 1
    for (int iter = 0; iter < NITER; iter++) {
        CP_WAIT1();
        __syncthreads();
        const int stage = iter & 1;
        const uint32_t sstage = sbase + (uint32_t)(stage * T1_SWORDS) * 4u;

        #pragma unroll
        for (int kc = 0; kc < 2; kc++) {
            uint32_t af[2][2][4];
            #pragma unroll
            for (int l = 0; l < 2; l++)
                #pragma unroll
                for (int mi = 0; mi < 2; mi++)
                    ldsm4(af[l][mi][0], af[l][mi][1], af[l][mi][2], af[l][mi][3],
                          sstage + (aw0 + (uint32_t)(l * LVLW + mi * 16 * RSW + kc * 8)) * 4u);

            uint32_t bf_[2][8][2];
            #pragma unroll
            for (int l = 0; l < 2; l++)
                #pragma unroll
                for (int p = 0; p < 4; p++) {
                    uint32_t r0, r1, r2, r3;
                    ldsm4(r0, r1, r2, r3,
                          sstage + (bw0 + (uint32_t)(l * LVLW + p * 16 * RSW + kc * 8)) * 4u);
                    bf_[l][2 * p][0]     = r0;  bf_[l][2 * p][1]     = r1;
                    bf_[l][2 * p + 1][0] = r2;  bf_[l][2 * p + 1][1] = r3;
                }

            #pragma unroll
            for (int mi = 0; mi < 2; mi++)
                #pragma unroll
                for (int ni = 0; ni < 8; ni++)
                    mma16h(acc[mi][ni], af[0][mi], bf_[0][ni]);
            #pragma unroll
            for (int mi = 0; mi < 2; mi++)
                #pragma unroll
                for (int ni = 0; ni < 8; ni++)
                    mma16h(acc[mi][ni], af[0][mi], bf_[1][ni]);
            #pragma unroll
            for (int mi = 0; mi < 2; mi++)
                #pragma unroll
                for (int ni = 0; ni < 8; ni++)
                    mma16h(acc[mi][ni], af[1][mi], bf_[0][ni]);
        }
        __syncthreads();
        if (iter + 2 < NITER)
            fill_t1(xa, xb, wa, wb, sidx, n0, (iter + 2) * 32, tid, stage, sbase);
        CP_COMMIT();
    }

    #pragma unroll
    for (int mi = 0; mi < 2; mi++)
        #pragma unroll
        for (int half = 0; half < 2; half++) {
            const int crow = m0 + warp_m * 32 + mi * 16 + g + half * 8;
            if (crow < nflag) {
                #pragma unroll
                for (int ni = 0; ni < 8; ni++) {
                    const int col = n0 + warp_n * 64 + ni * 8 + 2 * t;
                    float2 b = *(const float2*)(bias + col);
                    float2 r;
                    r.x = gelu_exact(acc[mi][ni][half * 2 + 0] + b.x);
                    r.y = gelu_exact(acc[mi][ni][half * 2 + 1] + b.y);
                    *(float2*)(out + (size_t)crow * HID + col) = r;
                }
            }
        }
}

// ---- TIER-2 exact repair: round-1 fp32 fmaf chain, gathered --------------
#define RBM 16

__global__ __launch_bounds__(256)
void gemm_repair(const float* __restrict__ x0, const float* __restrict__ x1,
                 const float* __restrict__ x2, const float* __restrict__ W,
                 const float* __restrict__ bias, float* __restrict__ out)
{
    const int nflag = g_nflag2;
    const int m0 = blockIdx.y * RBM;
    if (m0 >= nflag) return;
    __shared__ float As[16][RBM];
    __shared__ float Bs[16][128];

    const int tid = threadIdx.x;
    const int n0  = blockIdx.x * 128;
    const int r   = tid >> 4;
    const int c0  = (tid & 15) * 8;

    float acc[8];
    #pragma unroll
    for (int j = 0; j < 8; j++) acc[j] = 0.0f;

    for (int k0 = 0; k0 < KTOT; k0 += 16) {
        const int part = k0 / HID;
        const float* xp = (part == 0) ? x0 : ((part == 1) ? x1 : x2);
        const int kp = k0 - part * HID;

        {
            const int r2 = tid >> 4, kk = tid & 15;
            const int cr = (m0 + r2 < nflag) ? (m0 + r2) : 0;
            const int grow = g_flagidx2[cr];
            As[kk][r2] = xp[(size_t)grow * HID + kp + kk];
        }
        #pragma unroll
        for (int p = 0; p < 2; p++) {
            const int slot = tid + p * 256;
            const int row  = slot >> 2;
            const int vc   = (slot & 3) * 4;
            float4 bv = *reinterpret_cast<const float4*>(
                W + (size_t)(n0 + row) * KTOT + k0 + vc);
            Bs[vc + 0][row] = bv.x; Bs[vc + 1][row] = bv.y;
            Bs[vc + 2][row] = bv.z; Bs[vc + 3][row] = bv.w;
        }
        __syncthreads();

        #pragma unroll
        for (int kk = 0; kk < 16; kk++) {
            const float a = As[kk][r];
            #pragma unroll
            for (int j = 0; j < 8; j++)
                acc[j] = fmaf(a, Bs[kk][c0 + j], acc[j]);
        }
        __syncthreads();
    }

    const int crow = m0 + r;
    if (crow < nflag) {
        const size_t ro = (size_t)crow * HID + n0 + c0;
        #pragma unroll
        for (int j = 0; j < 8; j++)
            out[ro + j] = gelu_exact(acc[j] + bias[n0 + c0 + j]);
    }
}

// ------- main top-k from precomputed mma logits + tier-1 flagging ---------
__global__ __launch_bounds__(64)
void topk_from_logits(const float* __restrict__ logits, float* __restrict__ probs)
{
    __shared__ float lg[64][65];
    __shared__ float pv[64][2];
    __shared__ int   pi[64][2];

    const int n0 = blockIdx.x * 64;
    const int s  = threadIdx.x;

    #pragma unroll 8
    for (int r = 0; r < 64; r++)
        lg[r][s] = logits[(size_t)(n0 + r) * LPAD + s];
    __syncthreads();

    {
        float v1 = -3.4e38f, v2 = -3.4e38f, v3 = -3.4e38f;
        int   i1 = -1,       i2 = -1;
        #pragma unroll
        for (int j = 0; j < NS; j++) {
            float v = lg[s][j];
            if (v > v1)      { v3 = v2; v2 = v1; i2 = i1; v1 = v; i1 = j; }
            else if (v > v2) { v3 = v2; v2 = v;  i2 = j; }
            else if (v > v3) { v3 = v; }
        }
        const float e2  = expf(v2 - v1);
        const float inv = 1.0f / (1.0f + e2);
        pv[s][0] = inv;  pv[s][1] = e2 * inv;
        pi[s][0] = i1;   pi[s][1] = i2;
        if (v2 - v3 < TAU1) {
            int pos = atomicAdd(&g_nflag, 1);
            g_flagidx[pos] = n0 + s;
        }
    }
    __syncthreads();

    #pragma unroll 8
    for (int r = 0; r < 64; r++) {
        float p = 0.0f;
        if (s == pi[r][0])      p = pv[r][0];
        else if (s == pi[r][1]) p = pv[r][1];
        probs[(size_t)(n0 + r) * NS + s] = p;
    }
}

// ----------------------- replay logits kernels (exact fp32) ---------------
#define TTOK 8

__global__ void zero_flags_kernel() {
    if (threadIdx.x == 0) { g_nflag = 0; g_nflag2 = 0; }
}

template<int MODE>
__global__ __launch_bounds__(NS)
void logits_topk_kernel(const float* __restrict__ h,
                        const float* __restrict__ W2,
                        const float* __restrict__ b2,
                        float* __restrict__ probs)
{
    __shared__ float hs[TTOK][HID];
    __shared__ float lg[TTOK][NS];
    __shared__ float pv[TTOK][2];
    __shared__ int   pi[TTOK][2];

    const int n0 = blockIdx.x * TTOK;
    const int cnt = (MODE == 1) ? g_nflag : g_nflag2;
    if (n0 >= cnt) return;
    const int s  = threadIdx.x;

    {
        const float4* src = reinterpret_cast<const float4*>(h + (size_t)n0 * HID);
        float4* dst = reinterpret_cast<float4*>(&hs[0][0]);
        #pragma unroll
        for (int i = s; i < TTOK * HID / 4; i += NS) dst[i] = src[i];
    }
    __syncthreads();

    float acc[TTOK];
    #pragma unroll
    for (int tk = 0; tk < TTOK; tk++) acc[tk] = 0.0f;
    const float* w = W2 + (size_t)s * HID;
    for (int k = 0; k < HID; k += 4) {
        float4 wv = *reinterpret_cast<const float4*>(w + k);
        #pragma unroll
        for (int tk = 0; tk < TTOK; tk++) {
            acc[tk] = fmaf(wv.x, hs[tk][k + 0], acc[tk]);
            acc[tk] = fmaf(wv.y, hs[tk][k + 1], acc[tk]);
            acc[tk] = fmaf(wv.z, hs[tk][k + 2], acc[tk]);
            acc[tk] = fmaf(wv.w, hs[tk][k + 3], acc[tk]);
        }
    }
    const float bb = b2[s];
    #pragma unroll
    for (int tk = 0; tk < TTOK; tk++) lg[tk][s] = acc[tk] + bb;
    __syncthreads();

    if (s < TTOK && n0 + s < cnt) {
        float v1 = -3.4e38f, v2 = -3.4e38f, v3 = -3.4e38f;
        int   i1 = -1,       i2 = -1;
        #pragma unroll
        for (int j = 0; j < NS; j++) {
            float v = lg[s][j];
            if (v > v1)      { v3 = v2; v2 = v1; i2 = i1; v1 = v; i1 = j; }
            else if (v > v2) { v3 = v2; v2 = v;  i2 = j; }
            else if (v > v3) { v3 = v; }
        }
        const float e2  = expf(v2 - v1);
        const float inv = 1.0f / (1.0f + e2);
        pv[s][0] = inv;  pv[s][1] = e2 * inv;
        pi[s][0] = i1;   pi[s][1] = i2;
        if (MODE == 1 && (v2 - v3 < TAU2)) {
            int pos = atomicAdd(&g_nflag2, 1);
            g_flagidx2[pos] = g_flagidx[n0 + s];
        }
    }
    __syncthreads();

    #pragma unroll
    for (int tk = 0; tk < TTOK; tk++) {
        if (n0 + tk >= cnt) continue;
        float p = 0.0f;
        if (s == pi[tk][0])      p = pv[tk][0];
        else if (s == pi[tk][1]) p = pv[tk][1];
        const size_t row = (MODE == 1) ? (size_t)g_flagidx[n0 + tk]
                                       : (size_t)g_flagidx2[n0 + tk];
        probs[row * NS + s] = p;
    }
}

// ------------------------------ beta --------------------------------------
__global__ __launch_bounds__(128)
void beta_kernel(const float* __restrict__ hd, const float* __restrict__ Wd2,
                 const float* __restrict__ bd2, float* __restrict__ beta)
{
    const int warp = threadIdx.x >> 5;
    const int lane = threadIdx.x & 31;
    const int n = blockIdx.x * 4 + warp;
    const float* row = hd + (size_t)n * (HID / 2);
    float acc = 0.0f;
    #pragma unroll
    for (int k = lane * 4; k < HID / 2; k += 128) {
        float4 a = *reinterpret_cast<const float4*>(row + k);
        float4 w = *reinterpret_cast<const float4*>(Wd2 + k);
        acc += a.x * w.x + a.y * w.y + a.z * w.z + a.w * w.w;
    }
    #pragma unroll
    for (int o = 16; o > 0; o >>= 1) acc += __shfl_xor_sync(0xffffffffu, acc, o);
    if (lane == 0) beta[n] = 1.0f / (1.0f + expf(-(acc + bd2[0])));
}

// ---------------------------------------------------------------------------
extern "C" void kernel_launch(void* const* d_in, const int* in_sizes, int n_in,
                              void* d_out, int out_size)
{
    const float* sm  = (const float*)d_in[0];
    const float* tm  = (const float*)d_in[1];
    const float* dg  = (const float*)d_in[2];
    const float* W1  = (const float*)d_in[3];
    const float* b1  = (const float*)d_in[4];
    const float* W2  = (const float*)d_in[5];
    const float* b2  = (const float*)d_in[6];
    const float* Wd1 = (const float*)d_in[7];
    const float* bd1 = (const float*)d_in[8];
    const float* Wd2 = (const float*)d_in[9];
    const float* bd2 = (const float*)d_in[10];

    float* out   = (float*)d_out;
    float* probs = out;
    float* beta  = out + (size_t)NTOK * NS;

    float *hptr, *hdptr, *hrep, *hrep2, *logit, *b2p;
    __half *xh, *xl, *w1a, *w1b, *wdh, *w2h, *h16;
    cudaGetSymbolAddress((void**)&hptr,  g_h);
    cudaGetSymbolAddress((void**)&hdptr, g_hd);
    cudaGetSymbolAddress((void**)&hrep,  g_hrep);
    cudaGetSymbolAddress((void**)&hrep2, g_hrep2);
    cudaGetSymbolAddress((void**)&logit, g_logits);
    cudaGetSymbolAddress((void**)&b2p,   g_b2p);
    cudaGetSymbolAddress((void**)&xh,  g_xh);
    cudaGetSymbolAddress((void**)&xl,  g_xl);
    cudaGetSymbolAddress((void**)&w1a, g_w1a);
    cudaGetSymbolAddress((void**)&w1b, g_w1b);
    cudaGetSymbolAddress((void**)&wdh, g_wd);
    cudaGetSymbolAddress((void**)&w2h, g_w2h);
    cudaGetSymbolAddress((void**)&h16, g_h16);

    cudaFuncSetAttribute((const void*)gemm_big<KTOT, true, true>,
                         cudaFuncAttributeMaxDynamicSharedMemorySize, SMEM_BIG_BYTES);
    cudaFuncSetAttribute((const void*)gemm_big<HID, false, false>,
                         cudaFuncAttributeMaxDynamicSharedMemorySize, SMEM_BIG_BYTES);
    cudaFuncSetAttribute((const void*)gemm_t1_f16x3,
                         cudaFuncAttributeMaxDynamicSharedMemorySize, T1_SMEM_BYTES);

    zero_flags_kernel<<<1, 32>>>();

    {
        const int nblk = (NTOK * HID / 4 + 255) / 256;
        splitX2h<<<nblk, 256>>>(sm, xh, xl, 0);
        splitX2h<<<nblk, 256>>>(tm, xh, xl, HID);
        splitX2h<<<nblk, 256>>>(dg, xh, xl, 2 * HID);
        int n4 = HID * KTOT / 4;
        splitW2h<<<(n4 + 255) / 256, 256>>>(W1, w1a, w1b, n4);
        n4 = (HID / 2) * KTOT / 4;
        convWh<<<(n4 + 255) / 256, 256>>>(Wd1, wdh, n4);
        prepW2<<<(LPAD * HID + 255) / 256, 256>>>(W2, b2, w2h, b2p);
    }

    // main merged GEMM1 + GEMMd (big tile 256x128)
    {
        dim3 grid(HID / 128 + (HID / 2) / 128, NTOK / 256);   // (12, 128)
        gemm_big<KTOT, true, true><<<grid, 256, SMEM_BIG_BYTES>>>(
            xh, w1a, wdh, b1, bd1, hptr, hdptr, h16, HID / 128, HID, HID / 2);
    }

    // logits = h16 @ W2h^T (+b2p), fp32 out [NTOK, 128]
    {
        dim3 grid(1, NTOK / 256);
        gemm_big<HID, false, false><<<grid, 256, SMEM_BIG_BYTES>>>(
            h16, w2h, w2h, b2p, b2p, logit, logit, nullptr, 1, LPAD, LPAD);
    }

    // top-2 + softmax + tier-1 flagging
    topk_from_logits<<<NTOK / 64, 64>>>(logit, probs);

    // tier-1: gathered 3-term mma repair + exact fp32 replay (flags tier-2)
    {
        dim3 g1(HID / 128, NTOK / 128);
        gemm_t1_f16x3<<<g1, 256, T1_SMEM_BYTES>>>(xh, xl, w1a, w1b, b1, hrep);
        logits_topk_kernel<1><<<NTOK / TTOK, NS>>>(hrep, W2, b2, probs);
    }

    // tier-2: exact round-1 scalar replay
    {
        dim3 gr(HID / 128, NTOK / RBM);
        gemm_repair<<<gr, 256>>>(sm, tm, dg, W1, b1, hrep2);
        logits_topk_kernel<2><<<NTOK / TTOK, NS>>>(hrep2, W2, b2, probs);
    }

    beta_kernel<<<NTOK / 4, 128>>>(hdptr, Wd2, bd2, beta);
}

// round 15
// speedup vs baseline: 1.0915x; 1.0915x over previous
#include <cuda_runtime.h>
#include <cuda_fp16.h>
#include <math.h>
#include <stdint.h>

#define NTOK 32768
#define HID  1024
#define NS   64
#define KTOT 3072
#define LPAD 128
#define TAU1 3e-3f
#define TAU2 2e-5f

// ------------------------- device scratch ---------------------------------
__device__ float g_hd[(size_t)NTOK * (HID / 2)];
__device__ float g_hrep [(size_t)NTOK * HID];
__device__ float g_hrep2[(size_t)NTOK * HID];
__device__ float g_logits[(size_t)NTOK * LPAD];
__device__ __half g_h16[(size_t)NTOK * HID];
__device__ __half g_xh[(size_t)NTOK * KTOT];
__device__ __half g_xl[(size_t)NTOK * KTOT];
__device__ __half g_w1a[(size_t)HID * KTOT];
__device__ __half g_w1b[(size_t)HID * KTOT];
__device__ __half g_wd[(size_t)(HID / 2) * KTOT];
__device__ __half g_w2h[(size_t)LPAD * HID];
__device__ float  g_b2p[LPAD];
__device__ int g_nflag;
__device__ int g_flagidx[NTOK];
__device__ int g_nflag2;
__device__ int g_flagidx2[NTOK];

__device__ __forceinline__ float gelu_exact(float x) {
    return 0.5f * x * (1.0f + erff(x * 0.70710678118654752440f));
}
__device__ __forceinline__ void cp16(uint32_t d, const void* s) {
    asm volatile("cp.async.cg.shared.global [%0], [%1], 16;" :: "r"(d), "l"(s));
}
#define CP_COMMIT() asm volatile("cp.async.commit_group;" ::: "memory")
#define CP_WAIT1()  asm volatile("cp.async.wait_group 1;" ::: "memory")
#define CP_WAIT2()  asm volatile("cp.async.wait_group 2;" ::: "memory")
__device__ __forceinline__ void mma16h(float* c, const uint32_t* a, const uint32_t* b) {
    asm volatile("mma.sync.aligned.m16n8k16.row.col.f32.f16.f16.f32 "
        "{%0,%1,%2,%3}, {%4,%5,%6,%7}, {%8,%9}, {%0,%1,%2,%3};"
        : "+f"(c[0]), "+f"(c[1]), "+f"(c[2]), "+f"(c[3])
        : "r"(a[0]), "r"(a[1]), "r"(a[2]), "r"(a[3]), "r"(b[0]), "r"(b[1]));
}
__device__ __forceinline__ void ldsm4(uint32_t& r0, uint32_t& r1, uint32_t& r2,
                                      uint32_t& r3, uint32_t addr) {
    asm volatile("ldmatrix.sync.aligned.m8n8.x4.shared.b16 {%0,%1,%2,%3}, [%4];"
                 : "=r"(r0), "=r"(r1), "=r"(r2), "=r"(r3) : "r"(addr));
}

// ---------------------- prep kernels --------------------------------------
__device__ __forceinline__ void hsplit2(float x, uint16_t& s1, uint16_t& s2) {
    __half h1 = __float2half_rn(x);
    __half h2 = __float2half_rn(x - __half2float(h1));
    s1 = __half_as_ushort(h1);
    s2 = __half_as_ushort(h2);
}

// fused: all three X parts in one launch
__global__ __launch_bounds__(256)
void splitX2h_all(const float* __restrict__ x0, const float* __restrict__ x1,
                  const float* __restrict__ x2,
                  __half* __restrict__ oa, __half* __restrict__ ob)
{
    const int gid = blockIdx.x * 256 + threadIdx.x;      // over 3*NTOK*HID/4
    if (gid >= 3 * NTOK * HID / 4) return;
    const int part = gid / (NTOK * HID / 4);
    const int idx4 = gid - part * (NTOK * HID / 4);
    const float* in = (part == 0) ? x0 : ((part == 1) ? x1 : x2);
    const int n = idx4 >> 8, c4 = idx4 & 255;
    float4 v = reinterpret_cast<const float4*>(in)[idx4];
    uint16_t a[4], b[4];
    hsplit2(v.x, a[0], b[0]); hsplit2(v.y, a[1], b[1]);
    hsplit2(v.z, a[2], b[2]); hsplit2(v.w, a[3], b[3]);
    const size_t off = (size_t)n * KTOT + part * HID + c4 * 4;
    *reinterpret_cast<uint2*>(oa + off) =
        make_uint2((uint32_t)a[0] | ((uint32_t)a[1] << 16),
                   (uint32_t)a[2] | ((uint32_t)a[3] << 16));
    *reinterpret_cast<uint2*>(ob + off) =
        make_uint2((uint32_t)b[0] | ((uint32_t)b[1] << 16),
                   (uint32_t)b[2] | ((uint32_t)b[3] << 16));
}

__global__ __launch_bounds__(256)
void splitW2h(const float* __restrict__ in, __half* __restrict__ oa,
              __half* __restrict__ ob, int n4)
{
    const int idx4 = blockIdx.x * 256 + threadIdx.x;
    if (idx4 >= n4) return;
    float4 v = reinterpret_cast<const float4*>(in)[idx4];
    uint16_t a[4], b[4];
    hsplit2(v.x, a[0], b[0]); hsplit2(v.y, a[1], b[1]);
    hsplit2(v.z, a[2], b[2]); hsplit2(v.w, a[3], b[3]);
    const size_t off = (size_t)idx4 * 4;
    *reinterpret_cast<uint2*>(oa + off) =
        make_uint2((uint32_t)a[0] | ((uint32_t)a[1] << 16),
                   (uint32_t)a[2] | ((uint32_t)a[3] << 16));
    *reinterpret_cast<uint2*>(ob + off) =
        make_uint2((uint32_t)b[0] | ((uint32_t)b[1] << 16),
                   (uint32_t)b[2] | ((uint32_t)b[3] << 16));
}

__global__ __launch_bounds__(256)
void convWh(const float* __restrict__ in, __half* __restrict__ oa, int n4)
{
    const int idx4 = blockIdx.x * 256 + threadIdx.x;
    if (idx4 >= n4) return;
    float4 v = reinterpret_cast<const float4*>(in)[idx4];
    uint16_t a0 = __half_as_ushort(__float2half_rn(v.x));
    uint16_t a1 = __half_as_ushort(__float2half_rn(v.y));
    uint16_t a2 = __half_as_ushort(__float2half_rn(v.z));
    uint16_t a3 = __half_as_ushort(__float2half_rn(v.w));
    *reinterpret_cast<uint2*>(oa + (size_t)idx4 * 4) =
        make_uint2((uint32_t)a0 | ((uint32_t)a1 << 16),
                   (uint32_t)a2 | ((uint32_t)a3 << 16));
}

__global__ __launch_bounds__(256)
void prepW2(const float* __restrict__ W2, const float* __restrict__ b2,
            __half* __restrict__ w2h, float* __restrict__ b2p)
{
    const int idx = blockIdx.x * 256 + threadIdx.x;
    if (idx < LPAD * HID) {
        const int row = idx >> 10;
        float v = (row < NS) ? W2[(size_t)row * HID + (idx & 1023)] : 0.0f;
        w2h[idx] = __float2half_rn(v);
    }
    if (idx < LPAD) b2p[idx] = (idx < NS) ? b2[idx] : 0.0f;
}

// ---- MAIN fp16 1-term mma GEMM, ldmatrix, 3-stage (R13 proven kernel) ----
// OUTMODE: 0 = h-part writes h16 only / hd-part writes fp32 + GELU
//          1 = plain fp32 out + bias, no GELU (logits GEMM)
#define RSW   20
#define LVLW  (128 * RSW)
#define NITER (KTOT / 32)
#define NSTAGE 3
#define SWORDS (2 * LVLW)
#define SMEM_MMA_BYTES (NSTAGE * SWORDS * 4)   // 61440

static __device__ __forceinline__ void fill_stage2(
    const __half* __restrict__ xh, const __half* __restrict__ w,
    int m0, int n0, int k0, int tid, int stage, uint32_t sbase, int kstride)
{
    #pragma unroll
    for (int p = 0; p < 4; p++) {
        const int slot = p >> 1;
        const int c    = tid + (p & 1) * 256;
        const int row  = c >> 2;
        const int q    = c & 3;
        const __half* src = (slot == 0)
            ? xh + (size_t)(m0 + row) * kstride + k0 + q * 8
            : w  + (size_t)(n0 + row) * kstride + k0 + q * 8;
        const uint32_t dw = (uint32_t)(stage * SWORDS + slot * LVLW + row * RSW + q * 4);
        cp16(sbase + dw * 4u, src);
    }
}

template<int KDIM, int OUTMODE>
__global__ void __launch_bounds__(256)
gemm_f16x1(const __half* __restrict__ xh,
           const __half* __restrict__ w1, const __half* __restrict__ wd,
           const float* __restrict__ b1, const float* __restrict__ bd,
           float* __restrict__ out1, float* __restrict__ outd,
           __half* __restrict__ h16, int nblk1, int nout1, int nout2)
{
    extern __shared__ uint32_t smw[];
    const int bx = blockIdx.x;
    const bool first = (bx < nblk1);
    const __half* w    = first ? w1 : wd;
    const float* bias  = first ? b1 : bd;
    float* out         = first ? out1 : outd;
    const int Nout     = first ? nout1 : nout2;
    const int n0       = (first ? bx : bx - nblk1) * 128;

    const int tid  = threadIdx.x;
    const int lane = tid & 31;
    const int wid  = tid >> 5;
    const int g    = lane >> 2;
    const int t    = lane & 3;
    const int warp_m = wid >> 1;
    const int warp_n = wid & 1;
    const int m0 = blockIdx.y * 128;
    const uint32_t sbase = (uint32_t)__cvta_generic_to_shared(smw);

    const int la_row  = (lane & 7) + ((lane >> 3) & 1) * 8;
    const int la_colw = ((lane >> 4) & 1) * 4;
    const int lb_row  = (lane & 7) + ((lane >> 4) & 1) * 8;
    const int lb_colw = ((lane >> 3) & 1) * 4;
    const uint32_t aw0 = (uint32_t)((warp_m * 32 + la_row) * RSW + la_colw);
    const uint32_t bw0 = (uint32_t)(LVLW + (warp_n * 64 + lb_row) * RSW + lb_colw);

    float acc[2][8][4];
    #pragma unroll
    for (int mi = 0; mi < 2; mi++)
        #pragma unroll
        for (int ni = 0; ni < 8; ni++)
            #pragma unroll
            for (int q = 0; q < 4; q++) acc[mi][ni][q] = 0.0f;

    const int niter = KDIM / 32;
    fill_stage2(xh, w, m0, n0, 0,  tid, 0, sbase, KDIM); CP_COMMIT();
    fill_stage2(xh, w, m0, n0, 32, tid, 1, sbase, KDIM); CP_COMMIT();
    fill_stage2(xh, w, m0, n0, 64, tid, 2, sbase, KDIM); CP_COMMIT();

    int stage = 0;
    #pragma unroll 1
    for (int iter = 0; iter < niter; iter++) {
        CP_WAIT2();
        __syncthreads();
        const uint32_t sstage = sbase + (uint32_t)(stage * SWORDS) * 4u;

        #pragma unroll
        for (int kc = 0; kc < 2; kc++) {
            uint32_t af[2][4];
            #pragma unroll
            for (int mi = 0; mi < 2; mi++)
                ldsm4(af[mi][0], af[mi][1], af[mi][2], af[mi][3],
                      sstage + (aw0 + (uint32_t)(mi * 16 * RSW + kc * 8)) * 4u);

            uint32_t bf_[8][2];
            #pragma unroll
            for (int p = 0; p < 4; p++) {
                uint32_t r0, r1, r2, r3;
                ldsm4(r0, r1, r2, r3,
                      sstage + (bw0 + (uint32_t)(p * 16 * RSW + kc * 8)) * 4u);
                bf_[2 * p][0]     = r0;  bf_[2 * p][1]     = r1;
                bf_[2 * p + 1][0] = r2;  bf_[2 * p + 1][1] = r3;
            }

            #pragma unroll
            for (int mi = 0; mi < 2; mi++)
                #pragma unroll
                for (int ni = 0; ni < 8; ni++)
                    mma16h(acc[mi][ni], af[mi], bf_[ni]);
        }
        __syncthreads();
        if (iter + NSTAGE < niter)
            fill_stage2(xh, w, m0, n0, (iter + NSTAGE) * 32, tid, stage, sbase, KDIM);
        CP_COMMIT();
        stage = (stage == NSTAGE - 1) ? 0 : stage + 1;
    }

    #pragma unroll
    for (int mi = 0; mi < 2; mi++)
        #pragma unroll
        for (int half = 0; half < 2; half++) {
            const int row = m0 + warp_m * 32 + mi * 16 + g + half * 8;
            #pragma unroll
            for (int ni = 0; ni < 8; ni++) {
                const int col = n0 + warp_n * 64 + ni * 8 + 2 * t;
                float2 b = *(const float2*)(bias + col);
                float2 r;
                if (OUTMODE == 0) {
                    r.x = gelu_exact(acc[mi][ni][half * 2 + 0] + b.x);
                    r.y = gelu_exact(acc[mi][ni][half * 2 + 1] + b.y);
                    if (first) {
                        // h path: fp16 only (fp32 h is never read)
                        *(__half2*)(h16 + (size_t)row * HID + col) =
                            __floats2half2_rn(r.x, r.y);
                    } else {
                        *(float2*)(out + (size_t)row * Nout + col) = r;
                    }
                } else {
                    r.x = acc[mi][ni][half * 2 + 0] + b.x;
                    r.y = acc[mi][ni][half * 2 + 1] + b.y;
                    *(float2*)(out + (size_t)row * Nout + col) = r;
                }
            }
        }
}

// ---- TIER-1 repair: gathered 3-term fp16 mma GEMM (proven R12 kernel) ----
#define T1_SWORDS (4 * LVLW)
#define T1_SMEM_BYTES (2 * T1_SWORDS * 4)   // 81920

static __device__ __forceinline__ void fill_t1(
    const __half* __restrict__ xa, const __half* __restrict__ xb,
    const __half* __restrict__ wa, const __half* __restrict__ wb,
    const int* sidx, int n0, int k0, int tid, int stage, uint32_t sbase)
{
    const __half* srcs[4] = {xa, xb, wa, wb};
    #pragma unroll
    for (int p = 0; p < 8; p++) {
        const int slot = p >> 1;
        const int c    = tid + (p & 1) * 256;
        const int row  = c >> 2;
        const int q    = c & 3;
        const __half* src = (slot < 2)
            ? srcs[slot] + (size_t)sidx[row] * KTOT + k0 + q * 8
            : srcs[slot] + (size_t)(n0 + row) * KTOT + k0 + q * 8;
        const uint32_t dw = (uint32_t)(stage * T1_SWORDS + slot * LVLW + row * RSW + q * 4);
        cp16(sbase + dw * 4u, src);
    }
}

__global__ void __launch_bounds__(256)
gemm_t1_f16x3(const __half* __restrict__ xa, const __half* __restrict__ xb,
              const __half* __restrict__ wa, const __half* __restrict__ wb,
              const float* __restrict__ bias, float* __restrict__ out)
{
    const int nflag = g_nflag;
    const int m0 = blockIdx.y * 128;
    if (m0 >= nflag) return;
    extern __shared__ uint32_t smw[];
    __shared__ int sidx[128];

    const int tid  = threadIdx.x;
    const int lane = tid & 31;
    const int wid  = tid >> 5;
    const int g    = lane >> 2;
    const int t    = lane & 3;
    const int warp_m = wid >> 1;
    const int warp_n = wid & 1;
    const int n0 = blockIdx.x * 128;
    const uint32_t sbase = (uint32_t)__cvta_generic_to_shared(smw);

    if (tid < 128)
        sidx[tid] = g_flagidx[(m0 + tid < nflag) ? m0 + tid : 0];
    __syncthreads();

    const int la_row  = (lane & 7) + ((lane >> 3) & 1) * 8;
    const int la_colw = ((lane >> 4) & 1) * 4;
    const int lb_row  = (lane & 7) + ((lane >> 4) & 1) * 8;
    const int lb_colw = ((lane >> 3) & 1) * 4;
    const uint32_t aw0 = (uint32_t)((warp_m * 32 + la_row) * RSW + la_colw);
    const uint32_t bw0 = (uint32_t)(2 * LVLW + (warp_n * 64 + lb_row) * RSW + lb_colw);

    float acc[2][8][4];
    #pragma unroll
    for (int mi = 0; mi < 2; mi++)
        #pragma unroll
        for (int ni = 0; ni < 8; ni++)
            #pragma unroll
            for (int q = 0; q < 4; q++) acc[mi][ni][q] = 0.0f;

    fill_t1(xa, xb, wa, wb, sidx, n0, 0,  tid, 0, sbase); CP_COMMIT();
    fill_t1(xa, xb, wa, wb, sidx, n0, 32, tid, 1, sbase); CP_COMMIT();

    #pragma unroll 1
    for (int iter = 0; iter < NITER; iter++) {
        CP_WAIT1();
        __syncthreads();
        const int stage = iter & 1;
        const uint32_t sstage = sbase + (uint32_t)(stage * T1_SWORDS) * 4u;

        #pragma unroll
        for (int kc = 0; kc < 2; kc++) {
            uint32_t af[2][2][4];
            #pragma unroll
            for (int l = 0; l < 2; l++)
                #pragma unroll
                for (int mi = 0; mi < 2; mi++)
                    ldsm4(af[l][mi][0], af[l][mi][1], af[l][mi][2], af[l][mi][3],
                          sstage + (aw0 + (uint32_t)(l * LVLW + mi * 16 * RSW + kc * 8)) * 4u);

            uint32_t bf_[2][8][2];
            #pragma unroll
            for (int l = 0; l < 2; l++)
                #pragma unroll
                for (int p = 0; p < 4; p++) {
                    uint32_t r0, r1, r2, r3;
                    ldsm4(r0, r1, r2, r3,
                          sstage + (bw0 + (uint32_t)(l * LVLW + p * 16 * RSW + kc * 8)) * 4u);
                    bf_[l][2 * p][0]     = r0;  bf_[l][2 * p][1]     = r1;
                    bf_[l][2 * p + 1][0] = r2;  bf_[l][2 * p + 1][1] = r3;
                }

            #pragma unroll
            for (int mi = 0; mi < 2; mi++)
                #pragma unroll
                for (int ni = 0; ni < 8; ni++)
                    mma16h(acc[mi][ni], af[0][mi], bf_[0][ni]);
            #pragma unroll
            for (int mi = 0; mi < 2; mi++)
                #pragma unroll
                for (int ni = 0; ni < 8; ni++)
                    mma16h(acc[mi][ni], af[0][mi], bf_[1][ni]);
            #pragma unroll
            for (int mi = 0; mi < 2; mi++)
                #pragma unroll
                for (int ni = 0; ni < 8; ni++)
                    mma16h(acc[mi][ni], af[1][mi], bf_[0][ni]);
        }
        __syncthreads();
        if (iter + 2 < NITER)
            fill_t1(xa, xb, wa, wb, sidx, n0, (iter + 2) * 32, tid, stage, sbase);
        CP_COMMIT();
    }

    #pragma unroll
    for (int mi = 0; mi < 2; mi++)
        #pragma unroll
        for (int half = 0; half < 2; half++) {
            const int crow = m0 + warp_m * 32 + mi * 16 + g + half * 8;
            if (crow < nflag) {
                #pragma unroll
                for (int ni = 0; ni < 8; ni++) {
                    const int col = n0 + warp_n * 64 + ni * 8 + 2 * t;
                    float2 b = *(const float2*)(bias + col);
                    float2 r;
                    r.x = gelu_exact(acc[mi][ni][half * 2 + 0] + b.x);
                    r.y = gelu_exact(acc[mi][ni][half * 2 + 1] + b.y);
                    *(float2*)(out + (size_t)crow * HID + col) = r;
                }
            }
        }
}

// ---- TIER-2 exact repair: round-1 fp32 fmaf chain, gathered --------------
#define RBM 16

__global__ __launch_bounds__(256)
void gemm_repair(const float* __restrict__ x0, const float* __restrict__ x1,
                 const float* __restrict__ x2, const float* __restrict__ W,
                 const float* __restrict__ bias, float* __restrict__ out)
{
    const int nflag = g_nflag2;
    const int m0 = blockIdx.y * RBM;
    if (m0 >= nflag) return;
    __shared__ float As[16][RBM];
    __shared__ float Bs[16][128];

    const int tid = threadIdx.x;
    const int n0  = blockIdx.x * 128;
    const int r   = tid >> 4;
    const int c0  = (tid & 15) * 8;

    float acc[8];
    #pragma unroll
    for (int j = 0; j < 8; j++) acc[j] = 0.0f;

    for (int k0 = 0; k0 < KTOT; k0 += 16) {
        const int part = k0 / HID;
        const float* xp = (part == 0) ? x0 : ((part == 1) ? x1 : x2);
        const int kp = k0 - part * HID;

        {
            const int r2 = tid >> 4, kk = tid & 15;
            const int cr = (m0 + r2 < nflag) ? (m0 + r2) : 0;
            const int grow = g_flagidx2[cr];
            As[kk][r2] = xp[(size_t)grow * HID + kp + kk];
        }
        #pragma unroll
        for (int p = 0; p < 2; p++) {
            const int slot = tid + p * 256;
            const int row  = slot >> 2;
            const int vc   = (slot & 3) * 4;
            float4 bv = *reinterpret_cast<const float4*>(
                W + (size_t)(n0 + row) * KTOT + k0 + vc);
            Bs[vc + 0][row] = bv.x; Bs[vc + 1][row] = bv.y;
            Bs[vc + 2][row] = bv.z; Bs[vc + 3][row] = bv.w;
        }
        __syncthreads();

        #pragma unroll
        for (int kk = 0; kk < 16; kk++) {
            const float a = As[kk][r];
            #pragma unroll
            for (int j = 0; j < 8; j++)
                acc[j] = fmaf(a, Bs[kk][c0 + j], acc[j]);
        }
        __syncthreads();
    }

    const int crow = m0 + r;
    if (crow < nflag) {
        const size_t ro = (size_t)crow * HID + n0 + c0;
        #pragma unroll
        for (int j = 0; j < 8; j++)
            out[ro + j] = gelu_exact(acc[j] + bias[n0 + c0 + j]);
    }
}

// ------- main top-k from precomputed mma logits + tier-1 flagging ---------
__global__ __launch_bounds__(64)
void topk_from_logits(const float* __restrict__ logits, float* __restrict__ probs)
{
    __shared__ float lg[64][65];
    __shared__ float pv[64][2];
    __shared__ int   pi[64][2];

    const int n0 = blockIdx.x * 64;
    const int s  = threadIdx.x;

    #pragma unroll 8
    for (int r = 0; r < 64; r++)
        lg[r][s] = logits[(size_t)(n0 + r) * LPAD + s];
    __syncthreads();

    {
        float v1 = -3.4e38f, v2 = -3.4e38f, v3 = -3.4e38f;
        int   i1 = -1,       i2 = -1;
        #pragma unroll
        for (int j = 0; j < NS; j++) {
            float v = lg[s][j];
            if (v > v1)      { v3 = v2; v2 = v1; i2 = i1; v1 = v; i1 = j; }
            else if (v > v2) { v3 = v2; v2 = v;  i2 = j; }
            else if (v > v3) { v3 = v; }
        }
        const float e2  = expf(v2 - v1);
        const float inv = 1.0f / (1.0f + e2);
        pv[s][0] = inv;  pv[s][1] = e2 * inv;
        pi[s][0] = i1;   pi[s][1] = i2;
        if (v2 - v3 < TAU1) {
            int pos = atomicAdd(&g_nflag, 1);
            g_flagidx[pos] = n0 + s;
        }
    }
    __syncthreads();

    #pragma unroll 8
    for (int r = 0; r < 64; r++) {
        float p = 0.0f;
        if (s == pi[r][0])      p = pv[r][0];
        else if (s == pi[r][1]) p = pv[r][1];
        probs[(size_t)(n0 + r) * NS + s] = p;
    }
}

// ----------------------- replay logits kernels (exact fp32) ---------------
#define TTOK 8

__global__ void zero_flags_kernel() {
    if (threadIdx.x == 0) { g_nflag = 0; g_nflag2 = 0; }
}

template<int MODE>
__global__ __launch_bounds__(NS)
void logits_topk_kernel(const float* __restrict__ h,
                        const float* __restrict__ W2,
                        const float* __restrict__ b2,
                        float* __restrict__ probs)
{
    __shared__ float hs[TTOK][HID];
    __shared__ float lg[TTOK][NS];
    __shared__ float pv[TTOK][2];
    __shared__ int   pi[TTOK][2];

    const int n0 = blockIdx.x * TTOK;
    const int cnt = (MODE == 1) ? g_nflag : g_nflag2;
    if (n0 >= cnt) return;
    const int s  = threadIdx.x;

    {
        const float4* src = reinterpret_cast<const float4*>(h + (size_t)n0 * HID);
        float4* dst = reinterpret_cast<float4*>(&hs[0][0]);
        #pragma unroll
        for (int i = s; i < TTOK * HID / 4; i += NS) dst[i] = src[i];
    }
    __syncthreads();

    float acc[TTOK];
    #pragma unroll
    for (int tk = 0; tk < TTOK; tk++) acc[tk] = 0.0f;
    const float* w = W2 + (size_t)s * HID;
    for (int k = 0; k < HID; k += 4) {
        float4 wv = *reinterpret_cast<const float4*>(w + k);
        #pragma unroll
        for (int tk = 0; tk < TTOK; tk++) {
            acc[tk] = fmaf(wv.x, hs[tk][k + 0], acc[tk]);
            acc[tk] = fmaf(wv.y, hs[tk][k + 1], acc[tk]);
            acc[tk] = fmaf(wv.z, hs[tk][k + 2], acc[tk]);
            acc[tk] = fmaf(wv.w, hs[tk][k + 3], acc[tk]);
        }
    }
    const float bb = b2[s];
    #pragma unroll
    for (int tk = 0; tk < TTOK; tk++) lg[tk][s] = acc[tk] + bb;
    __syncthreads();

    if (s < TTOK && n0 + s < cnt) {
        float v1 = -3.4e38f, v2 = -3.4e38f, v3 = -3.4e38f;
        int   i1 = -1,       i2 = -1;
        #pragma unroll
        for (int j = 0; j < NS; j++) {
            float v = lg[s][j];
            if (v > v1)      { v3 = v2; v2 = v1; i2 = i1; v1 = v; i1 = j; }
            else if (v > v2) { v3 = v2; v2 = v;  i2 = j; }
            else if (v > v3) { v3 = v; }
        }
        const float e2  = expf(v2 - v1);
        const float inv = 1.0f / (1.0f + e2);
        pv[s][0] = inv;  pv[s][1] = e2 * inv;
        pi[s][0] = i1;   pi[s][1] = i2;
        if (MODE == 1 && (v2 - v3 < TAU2)) {
            int pos = atomicAdd(&g_nflag2, 1);
            g_flagidx2[pos] = g_flagidx[n0 + s];
        }
    }
    __syncthreads();

    #pragma unroll
    for (int tk = 0; tk < TTOK; tk++) {
        if (n0 + tk >= cnt) continue;
        float p = 0.0f;
        if (s == pi[tk][0])      p = pv[tk][0];
        else if (s == pi[tk][1]) p = pv[tk][1];
        const size_t row = (MODE == 1) ? (size_t)g_flagidx[n0 + tk]
                                       : (size_t)g_flagidx2[n0 + tk];
        probs[row * NS + s] = p;
    }
}

// ------------------------------ beta --------------------------------------
__global__ __launch_bounds__(128)
void beta_kernel(const float* __restrict__ hd, const float* __restrict__ Wd2,
                 const float* __restrict__ bd2, float* __restrict__ beta)
{
    const int warp = threadIdx.x >> 5;
    const int lane = threadIdx.x & 31;
    const int n = blockIdx.x * 4 + warp;
    const float* row = hd + (size_t)n * (HID / 2);
    float acc = 0.0f;
    #pragma unroll
    for (int k = lane * 4; k < HID / 2; k += 128) {
        float4 a = *reinterpret_cast<const float4*>(row + k);
        float4 w = *reinterpret_cast<const float4*>(Wd2 + k);
        acc += a.x * w.x + a.y * w.y + a.z * w.z + a.w * w.w;
    }
    #pragma unroll
    for (int o = 16; o > 0; o >>= 1) acc += __shfl_xor_sync(0xffffffffu, acc, o);
    if (lane == 0) beta[n] = 1.0f / (1.0f + expf(-(acc + bd2[0])));
}

// ---------------------------------------------------------------------------
extern "C" void kernel_launch(void* const* d_in, const int* in_sizes, int n_in,
                              void* d_out, int out_size)
{
    const float* sm  = (const float*)d_in[0];
    const float* tm  = (const float*)d_in[1];
    const float* dg  = (const float*)d_in[2];
    const float* W1  = (const float*)d_in[3];
    const float* b1  = (const float*)d_in[4];
    const float* W2  = (const float*)d_in[5];
    const float* b2  = (const float*)d_in[6];
    const float* Wd1 = (const float*)d_in[7];
    const float* bd1 = (const float*)d_in[8];
    const float* Wd2 = (const float*)d_in[9];
    const float* bd2 = (const float*)d_in[10];

    float* out   = (float*)d_out;
    float* probs = out;
    float* beta  = out + (size_t)NTOK * NS;

    float *hdptr, *hrep, *hrep2, *logit, *b2p;
    __half *xh, *xl, *w1a, *w1b, *wdh, *w2h, *h16;
    cudaGetSymbolAddress((void**)&hdptr, g_hd);
    cudaGetSymbolAddress((void**)&hrep,  g_hrep);
    cudaGetSymbolAddress((void**)&hrep2, g_hrep2);
    cudaGetSymbolAddress((void**)&logit, g_logits);
    cudaGetSymbolAddress((void**)&b2p,   g_b2p);
    cudaGetSymbolAddress((void**)&xh,  g_xh);
    cudaGetSymbolAddress((void**)&xl,  g_xl);
    cudaGetSymbolAddress((void**)&w1a, g_w1a);
    cudaGetSymbolAddress((void**)&w1b, g_w1b);
    cudaGetSymbolAddress((void**)&wdh, g_wd);
    cudaGetSymbolAddress((void**)&w2h, g_w2h);
    cudaGetSymbolAddress((void**)&h16, g_h16);

    cudaFuncSetAttribute((const void*)gemm_f16x1<KTOT, 0>,
                         cudaFuncAttributeMaxDynamicSharedMemorySize, SMEM_MMA_BYTES);
    cudaFuncSetAttribute((const void*)gemm_f16x1<HID, 1>,
                         cudaFuncAttributeMaxDynamicSharedMemorySize, SMEM_MMA_BYTES);
    cudaFuncSetAttribute((const void*)gemm_t1_f16x3,
                         cudaFuncAttributeMaxDynamicSharedMemorySize, T1_SMEM_BYTES);

    zero_flags_kernel<<<1, 32>>>();

    {
        const int nblkX = (3 * NTOK * HID / 4 + 255) / 256;
        splitX2h_all<<<nblkX, 256>>>(sm, tm, dg, xh, xl);
        int n4 = HID * KTOT / 4;
        splitW2h<<<(n4 + 255) / 256, 256>>>(W1, w1a, w1b, n4);
        n4 = (HID / 2) * KTOT / 4;
        convWh<<<(n4 + 255) / 256, 256>>>(Wd1, wdh, n4);
        prepW2<<<(LPAD * HID + 255) / 256, 256>>>(W2, b2, w2h, b2p);
    }

    // main merged GEMM1 + GEMMd (h -> fp16 only; hd -> fp32)
    {
        dim3 grid(HID / 128 + (HID / 2) / 128, NTOK / 128);   // (12, 256)
        gemm_f16x1<KTOT, 0><<<grid, 256, SMEM_MMA_BYTES>>>(
            xh, w1a, wdh, b1, bd1, nullptr, hdptr, h16, HID / 128, HID, HID / 2);
    }

    // logits = h16 @ W2h^T (+b2p), fp32 out [NTOK, 128]
    {
        dim3 grid(1, NTOK / 128);
        gemm_f16x1<HID, 1><<<grid, 256, SMEM_MMA_BYTES>>>(
            h16, w2h, w2h, b2p, b2p, logit, logit, nullptr, 1, LPAD, LPAD);
    }

    // top-2 + softmax + tier-1 flagging
    topk_from_logits<<<NTOK / 64, 64>>>(logit, probs);

    // tier-1: gathered 3-term mma repair + exact fp32 replay (flags tier-2)
    {
        dim3 g1(HID / 128, NTOK / 128);
        gemm_t1_f16x3<<<g1, 256, T1_SMEM_BYTES>>>(xh, xl, w1a, w1b, b1, hrep);
        logits_topk_kernel<1><<<NTOK / TTOK, NS>>>(hrep, W2, b2, probs);
    }

    // tier-2: exact round-1 scalar replay
    {
        dim3 gr(HID / 128, NTOK / RBM);
        gemm_repair<<<gr, 256>>>(sm, tm, dg, W1, b1, hrep2);
        logits_topk_kernel<2><<<NTOK / TTOK, NS>>>(hrep2, W2, b2, probs);
    }

    beta_kernel<<<NTOK / 4, 128>>>(hdptr, Wd2, bd2, beta);
}

// round 16
// speedup vs baseline: 1.1030x; 1.0106x over previous
#include <cuda_runtime.h>
#include <cuda_fp16.h>
#include <math.h>
#include <stdint.h>

#define NTOK 32768
#define HID  1024
#define NS   64
#define KTOT 3072
#define LPAD 128
#define TAU1 3e-3f
#define TAU2 2e-5f

// ------------------------- device scratch ---------------------------------
__device__ float g_z  [(size_t)NTOK * HID];      // pre-GELU h accumulator (+b1)
__device__ __half g_hd16[(size_t)NTOK * (HID / 2)];
__device__ float g_hrep [(size_t)NTOK * HID];
__device__ float g_hrep2[(size_t)NTOK * HID];
__device__ float g_logits[(size_t)NTOK * LPAD];
__device__ __half g_h16[(size_t)NTOK * HID];
__device__ __half g_xh[(size_t)NTOK * KTOT];
__device__ __half g_xl[(size_t)NTOK * KTOT];
__device__ __half g_w1a[(size_t)HID * KTOT];
__device__ __half g_w1b[(size_t)HID * KTOT];
__device__ __half g_wd[(size_t)(HID / 2) * KTOT];
__device__ __half g_w2h[(size_t)LPAD * HID];
__device__ float  g_b2p[LPAD];
__device__ int g_nflag;
__device__ int g_flagidx[NTOK];
__device__ int g_nflag2;
__device__ int g_flagidx2[NTOK];

__device__ __forceinline__ float gelu_exact(float x) {
    return 0.5f * x * (1.0f + erff(x * 0.70710678118654752440f));
}
__device__ __forceinline__ void cp16(uint32_t d, const void* s) {
    asm volatile("cp.async.cg.shared.global [%0], [%1], 16;" :: "r"(d), "l"(s));
}
#define CP_COMMIT() asm volatile("cp.async.commit_group;" ::: "memory")
#define CP_WAIT1()  asm volatile("cp.async.wait_group 1;" ::: "memory")
#define CP_WAIT2()  asm volatile("cp.async.wait_group 2;" ::: "memory")
__device__ __forceinline__ void mma16h(float* c, const uint32_t* a, const uint32_t* b) {
    asm volatile("mma.sync.aligned.m16n8k16.row.col.f32.f16.f16.f32 "
        "{%0,%1,%2,%3}, {%4,%5,%6,%7}, {%8,%9}, {%0,%1,%2,%3};"
        : "+f"(c[0]), "+f"(c[1]), "+f"(c[2]), "+f"(c[3])
        : "r"(a[0]), "r"(a[1]), "r"(a[2]), "r"(a[3]), "r"(b[0]), "r"(b[1]));
}
__device__ __forceinline__ void ldsm4(uint32_t& r0, uint32_t& r1, uint32_t& r2,
                                      uint32_t& r3, uint32_t addr) {
    asm volatile("ldmatrix.sync.aligned.m8n8.x4.shared.b16 {%0,%1,%2,%3}, [%4];"
                 : "=r"(r0), "=r"(r1), "=r"(r2), "=r"(r3) : "r"(addr));
}

// ---------------------- prep kernels --------------------------------------
__device__ __forceinline__ void hsplit2(float x, uint16_t& s1, uint16_t& s2) {
    __half h1 = __float2half_rn(x);
    __half h2 = __float2half_rn(x - __half2float(h1));
    s1 = __half_as_ushort(h1);
    s2 = __half_as_ushort(h2);
}

__global__ __launch_bounds__(256)
void splitX2h_all(const float* __restrict__ x0, const float* __restrict__ x1,
                  const float* __restrict__ x2,
                  __half* __restrict__ oa, __half* __restrict__ ob)
{
    const int gid = blockIdx.x * 256 + threadIdx.x;
    if (gid >= 3 * NTOK * HID / 4) return;
    const int part = gid / (NTOK * HID / 4);
    const int idx4 = gid - part * (NTOK * HID / 4);
    const float* in = (part == 0) ? x0 : ((part == 1) ? x1 : x2);
    const int n = idx4 >> 8, c4 = idx4 & 255;
    float4 v = reinterpret_cast<const float4*>(in)[idx4];
    uint16_t a[4], b[4];
    hsplit2(v.x, a[0], b[0]); hsplit2(v.y, a[1], b[1]);
    hsplit2(v.z, a[2], b[2]); hsplit2(v.w, a[3], b[3]);
    const size_t off = (size_t)n * KTOT + part * HID + c4 * 4;
    *reinterpret_cast<uint2*>(oa + off) =
        make_uint2((uint32_t)a[0] | ((uint32_t)a[1] << 16),
                   (uint32_t)a[2] | ((uint32_t)a[3] << 16));
    *reinterpret_cast<uint2*>(ob + off) =
        make_uint2((uint32_t)b[0] | ((uint32_t)b[1] << 16),
                   (uint32_t)b[2] | ((uint32_t)b[3] << 16));
}

__global__ __launch_bounds__(256)
void splitW2h(const float* __restrict__ in, __half* __restrict__ oa,
              __half* __restrict__ ob, int n4)
{
    const int idx4 = blockIdx.x * 256 + threadIdx.x;
    if (idx4 >= n4) return;
    float4 v = reinterpret_cast<const float4*>(in)[idx4];
    uint16_t a[4], b[4];
    hsplit2(v.x, a[0], b[0]); hsplit2(v.y, a[1], b[1]);
    hsplit2(v.z, a[2], b[2]); hsplit2(v.w, a[3], b[3]);
    const size_t off = (size_t)idx4 * 4;
    *reinterpret_cast<uint2*>(oa + off) =
        make_uint2((uint32_t)a[0] | ((uint32_t)a[1] << 16),
                   (uint32_t)a[2] | ((uint32_t)a[3] << 16));
    *reinterpret_cast<uint2*>(ob + off) =
        make_uint2((uint32_t)b[0] | ((uint32_t)b[1] << 16),
                   (uint32_t)b[2] | ((uint32_t)b[3] << 16));
}

__global__ __launch_bounds__(256)
void convWh(const float* __restrict__ in, __half* __restrict__ oa, int n4)
{
    const int idx4 = blockIdx.x * 256 + threadIdx.x;
    if (idx4 >= n4) return;
    float4 v = reinterpret_cast<const float4*>(in)[idx4];
    uint16_t a0 = __half_as_ushort(__float2half_rn(v.x));
    uint16_t a1 = __half_as_ushort(__float2half_rn(v.y));
    uint16_t a2 = __half_as_ushort(__float2half_rn(v.z));
    uint16_t a3 = __half_as_ushort(__float2half_rn(v.w));
    *reinterpret_cast<uint2*>(oa + (size_t)idx4 * 4) =
        make_uint2((uint32_t)a0 | ((uint32_t)a1 << 16),
                   (uint32_t)a2 | ((uint32_t)a3 << 16));
}

// also zeroes flag counters (fused)
__global__ __launch_bounds__(256)
void prepW2(const float* __restrict__ W2, const float* __restrict__ b2,
            __half* __restrict__ w2h, float* __restrict__ b2p)
{
    const int idx = blockIdx.x * 256 + threadIdx.x;
    if (idx == 0) { g_nflag = 0; g_nflag2 = 0; }
    if (idx < LPAD * HID) {
        const int row = idx >> 10;
        float v = (row < NS) ? W2[(size_t)row * HID + (idx & 1023)] : 0.0f;
        w2h[idx] = __float2half_rn(v);
    }
    if (idx < LPAD) b2p[idx] = (idx < NS) ? b2[idx] : 0.0f;
}

// ---- MAIN fp16 1-term mma GEMM, ldmatrix, 3-stage (proven skeleton) ------
// OUTMODE 0: h-part -> h16 + z (pre-GELU fp32); hd-part -> fp16 hd + GELU
// OUTMODE 1: plain fp32 out + bias (logits GEMM)
#define RSW   20
#define LVLW  (128 * RSW)
#define NITER (KTOT / 32)
#define NSTAGE 3
#define SWORDS (2 * LVLW)
#define SMEM_MMA_BYTES (NSTAGE * SWORDS * 4)   // 61440

static __device__ __forceinline__ void fill_stage2(
    const __half* __restrict__ xh, const __half* __restrict__ w,
    int m0, int n0, int k0, int tid, int stage, uint32_t sbase, int kstride)
{
    #pragma unroll
    for (int p = 0; p < 4; p++) {
        const int slot = p >> 1;
        const int c    = tid + (p & 1) * 256;
        const int row  = c >> 2;
        const int q    = c & 3;
        const __half* src = (slot == 0)
            ? xh + (size_t)(m0 + row) * kstride + k0 + q * 8
            : w  + (size_t)(n0 + row) * kstride + k0 + q * 8;
        const uint32_t dw = (uint32_t)(stage * SWORDS + slot * LVLW + row * RSW + q * 4);
        cp16(sbase + dw * 4u, src);
    }
}

template<int KDIM, int OUTMODE>
__global__ void __launch_bounds__(256)
gemm_f16x1(const __half* __restrict__ xh,
           const __half* __restrict__ w1, const __half* __restrict__ wd,
           const float* __restrict__ b1, const float* __restrict__ bd,
           float* __restrict__ out1, __half* __restrict__ outd16,
           __half* __restrict__ h16, float* __restrict__ zout,
           int nblk1, int nout1, int nout2)
{
    extern __shared__ uint32_t smw[];
    const int bx = blockIdx.x;
    const bool first = (bx < nblk1);
    const __half* w    = first ? w1 : wd;
    const float* bias  = first ? b1 : bd;
    const int Nout     = first ? nout1 : nout2;
    const int n0       = (first ? bx : bx - nblk1) * 128;

    const int tid  = threadIdx.x;
    const int lane = tid & 31;
    const int wid  = tid >> 5;
    const int g    = lane >> 2;
    const int t    = lane & 3;
    const int warp_m = wid >> 1;
    const int warp_n = wid & 1;
    const int m0 = blockIdx.y * 128;
    const uint32_t sbase = (uint32_t)__cvta_generic_to_shared(smw);

    const int la_row  = (lane & 7) + ((lane >> 3) & 1) * 8;
    const int la_colw = ((lane >> 4) & 1) * 4;
    const int lb_row  = (lane & 7) + ((lane >> 4) & 1) * 8;
    const int lb_colw = ((lane >> 3) & 1) * 4;
    const uint32_t aw0 = (uint32_t)((warp_m * 32 + la_row) * RSW + la_colw);
    const uint32_t bw0 = (uint32_t)(LVLW + (warp_n * 64 + lb_row) * RSW + lb_colw);

    float acc[2][8][4];
    #pragma unroll
    for (int mi = 0; mi < 2; mi++)
        #pragma unroll
        for (int ni = 0; ni < 8; ni++)
            #pragma unroll
            for (int q = 0; q < 4; q++) acc[mi][ni][q] = 0.0f;

    const int niter = KDIM / 32;
    fill_stage2(xh, w, m0, n0, 0,  tid, 0, sbase, KDIM); CP_COMMIT();
    fill_stage2(xh, w, m0, n0, 32, tid, 1, sbase, KDIM); CP_COMMIT();
    fill_stage2(xh, w, m0, n0, 64, tid, 2, sbase, KDIM); CP_COMMIT();

    int stage = 0;
    #pragma unroll 1
    for (int iter = 0; iter < niter; iter++) {
        CP_WAIT2();
        __syncthreads();
        const uint32_t sstage = sbase + (uint32_t)(stage * SWORDS) * 4u;

        #pragma unroll
        for (int kc = 0; kc < 2; kc++) {
            uint32_t af[2][4];
            #pragma unroll
            for (int mi = 0; mi < 2; mi++)
                ldsm4(af[mi][0], af[mi][1], af[mi][2], af[mi][3],
                      sstage + (aw0 + (uint32_t)(mi * 16 * RSW + kc * 8)) * 4u);

            uint32_t bf_[8][2];
            #pragma unroll
            for (int p = 0; p < 4; p++) {
                uint32_t r0, r1, r2, r3;
                ldsm4(r0, r1, r2, r3,
                      sstage + (bw0 + (uint32_t)(p * 16 * RSW + kc * 8)) * 4u);
                bf_[2 * p][0]     = r0;  bf_[2 * p][1]     = r1;
                bf_[2 * p + 1][0] = r2;  bf_[2 * p + 1][1] = r3;
            }

            #pragma unroll
            for (int mi = 0; mi < 2; mi++)
                #pragma unroll
                for (int ni = 0; ni < 8; ni++)
                    mma16h(acc[mi][ni], af[mi], bf_[ni]);
        }
        __syncthreads();
        if (iter + NSTAGE < niter)
            fill_stage2(xh, w, m0, n0, (iter + NSTAGE) * 32, tid, stage, sbase, KDIM);
        CP_COMMIT();
        stage = (stage == NSTAGE - 1) ? 0 : stage + 1;
    }

    #pragma unroll
    for (int mi = 0; mi < 2; mi++)
        #pragma unroll
        for (int half = 0; half < 2; half++) {
            const int row = m0 + warp_m * 32 + mi * 16 + g + half * 8;
            #pragma unroll
            for (int ni = 0; ni < 8; ni++) {
                const int col = n0 + warp_n * 64 + ni * 8 + 2 * t;
                float2 b = *(const float2*)(bias + col);
                float2 z;
                z.x = acc[mi][ni][half * 2 + 0] + b.x;
                z.y = acc[mi][ni][half * 2 + 1] + b.y;
                if (OUTMODE == 0) {
                    float2 r;
                    r.x = gelu_exact(z.x);
                    r.y = gelu_exact(z.y);
                    if (first) {
                        *(__half2*)(h16 + (size_t)row * HID + col) =
                            __floats2half2_rn(r.x, r.y);
                        *(float2*)(zout + (size_t)row * HID + col) = z;
                    } else {
                        *(__half2*)(outd16 + (size_t)row * Nout + col) =
                            __floats2half2_rn(r.x, r.y);
                    }
                } else {
                    *(float2*)(out1 + (size_t)row * Nout + col) = z;
                }
            }
        }
}

// ---- TIER-1 repair: gathered 2-term DELTA mma GEMM (+ z cache) -----------
#define T1_SWORDS (4 * LVLW)
#define T1_SMEM_BYTES (2 * T1_SWORDS * 4)   // 81920

static __device__ __forceinline__ void fill_t1(
    const __half* __restrict__ xa, const __half* __restrict__ xb,
    const __half* __restrict__ wa, const __half* __restrict__ wb,
    const int* sidx, int n0, int k0, int tid, int stage, uint32_t sbase)
{
    const __half* srcs[4] = {xa, xb, wa, wb};
    #pragma unroll
    for (int p = 0; p < 8; p++) {
        const int slot = p >> 1;
        const int c    = tid + (p & 1) * 256;
        const int row  = c >> 2;
        const int q    = c & 3;
        const __half* src = (slot < 2)
            ? srcs[slot] + (size_t)sidx[row] * KTOT + k0 + q * 8
            : srcs[slot] + (size_t)(n0 + row) * KTOT + k0 + q * 8;
        const uint32_t dw = (uint32_t)(stage * T1_SWORDS + slot * LVLW + row * RSW + q * 4);
        cp16(sbase + dw * 4u, src);
    }
}

__global__ void __launch_bounds__(256)
gemm_t1_delta(const __half* __restrict__ xa, const __half* __restrict__ xb,
              const __half* __restrict__ wa, const __half* __restrict__ wb,
              const float* __restrict__ z, float* __restrict__ out)
{
    const int nflag = g_nflag;
    const int m0 = blockIdx.y * 128;
    if (m0 >= nflag) return;
    extern __shared__ uint32_t smw[];
    __shared__ int sidx[128];

    const int tid  = threadIdx.x;
    const int lane = tid & 31;
    const int wid  = tid >> 5;
    const int g    = lane >> 2;
    const int t    = lane & 3;
    const int warp_m = wid >> 1;
    const int warp_n = wid & 1;
    const int n0 = blockIdx.x * 128;
    const uint32_t sbase = (uint32_t)__cvta_generic_to_shared(smw);

    if (tid < 128)
        sidx[tid] = g_flagidx[(m0 + tid < nflag) ? m0 + tid : 0];
    __syncthreads();

    const int la_row  = (lane & 7) + ((lane >> 3) & 1) * 8;
    const int la_colw = ((lane >> 4) & 1) * 4;
    const int lb_row  = (lane & 7) + ((lane >> 4) & 1) * 8;
    const int lb_colw = ((lane >> 3) & 1) * 4;
    const uint32_t aw0 = (uint32_t)((warp_m * 32 + la_row) * RSW + la_colw);
    const uint32_t bw0 = (uint32_t)(2 * LVLW + (warp_n * 64 + lb_row) * RSW + lb_colw);

    float acc[2][8][4];
    #pragma unroll
    for (int mi = 0; mi < 2; mi++)
        #pragma unroll
        for (int ni = 0; ni < 8; ni++)
            #pragma unroll
            for (int q = 0; q < 4; q++) acc[mi][ni][q] = 0.0f;

    fill_t1(xa, xb, wa, wb, sidx, n0, 0,  tid, 0, sbase); CP_COMMIT();
    fill_t1(xa, xb, wa, wb, sidx, n0, 32, tid, 1, sbase); CP_COMMIT();

    #pragma unroll 1
    for (int iter = 0; iter < NITER; iter++) {
        CP_WAIT1();
        __syncthreads();
        const int stage = iter & 1;
        const uint32_t sstage = sbase + (uint32_t)(stage * T1_SWORDS) * 4u;

        #pragma unroll
        for (int kc = 0; kc < 2; kc++) {
            uint32_t af[2][2][4];
            #pragma unroll
            for (int l = 0; l < 2; l++)
                #pragma unroll
                for (int mi = 0; mi < 2; mi++)
                    ldsm4(af[l][mi][0], af[l][mi][1], af[l][mi][2], af[l][mi][3],
                          sstage + (aw0 + (uint32_t)(l * LVLW + mi * 16 * RSW + kc * 8)) * 4u);

            uint32_t bf_[2][8][2];
            #pragma unroll
            for (int l = 0; l < 2; l++)
                #pragma unroll
                for (int p = 0; p < 4; p++) {
                    uint32_t r0, r1, r2, r3;
                    ldsm4(r0, r1, r2, r3,
                          sstage + (bw0 + (uint32_t)(l * LVLW + p * 16 * RSW + kc * 8)) * 4u);
                    bf_[l][2 * p][0]     = r0;  bf_[l][2 * p][1]     = r1;
                    bf_[l][2 * p + 1][0] = r2;  bf_[l][2 * p + 1][1] = r3;
                }

            // delta = xh*wl + xl*wh   (the xh*wh bulk lives in z)
            #pragma unroll
            for (int mi = 0; mi < 2; mi++)
                #pragma unroll
                for (int ni = 0; ni < 8; ni++)
                    mma16h(acc[mi][ni], af[0][mi], bf_[1][ni]);
            #pragma unroll
            for (int mi = 0; mi < 2; mi++)
                #pragma unroll
                for (int ni = 0; ni < 8; ni++)
                    mma16h(acc[mi][ni], af[1][mi], bf_[0][ni]);
        }
        __syncthreads();
        if (iter + 2 < NITER)
            fill_t1(xa, xb, wa, wb, sidx, n0, (iter + 2) * 32, tid, stage, sbase);
        CP_COMMIT();
    }

    #pragma unroll
    for (int mi = 0; mi < 2; mi++)
        #pragma unroll
        for (int half = 0; half < 2; half++) {
            const int crow = m0 + warp_m * 32 + mi * 16 + g + half * 8;
            if (crow < nflag) {
                const size_t zrow = (size_t)sidx[warp_m * 32 + mi * 16 + g + half * 8] * HID;
                #pragma unroll
                for (int ni = 0; ni < 8; ni++) {
                    const int col = n0 + warp_n * 64 + ni * 8 + 2 * t;
                    float2 zv = *(const float2*)(z + zrow + col);
                    float2 r;
                    r.x = gelu_exact(zv.x + acc[mi][ni][half * 2 + 0]);
                    r.y = gelu_exact(zv.y + acc[mi][ni][half * 2 + 1]);
                    *(float2*)(out + (size_t)crow * HID + col) = r;
                }
            }
        }
}

// ---- TIER-2 exact repair: round-1 fp32 fmaf chain, gathered --------------
#define RBM 16

__global__ __launch_bounds__(256)
void gemm_repair(const float* __restrict__ x0, const float* __restrict__ x1,
                 const float* __restrict__ x2, const float* __restrict__ W,
                 const float* __restrict__ bias, float* __restrict__ out)
{
    const int nflag = g_nflag2;
    const int m0 = blockIdx.y * RBM;
    if (m0 >= nflag) return;
    __shared__ float As[16][RBM];
    __shared__ float Bs[16][128];

    const int tid = threadIdx.x;
    const int n0  = blockIdx.x * 128;
    const int r   = tid >> 4;
    const int c0  = (tid & 15) * 8;

    float acc[8];
    #pragma unroll
    for (int j = 0; j < 8; j++) acc[j] = 0.0f;

    for (int k0 = 0; k0 < KTOT; k0 += 16) {
        const int part = k0 / HID;
        const float* xp = (part == 0) ? x0 : ((part == 1) ? x1 : x2);
        const int kp = k0 - part * HID;

        {
            const int r2 = tid >> 4, kk = tid & 15;
            const int cr = (m0 + r2 < nflag) ? (m0 + r2) : 0;
            const int grow = g_flagidx2[cr];
            As[kk][r2] = xp[(size_t)grow * HID + kp + kk];
        }
        #pragma unroll
        for (int p = 0; p < 2; p++) {
            const int slot = tid + p * 256;
            const int row  = slot >> 2;
            const int vc   = (slot & 3) * 4;
            float4 bv = *reinterpret_cast<const float4*>(
                W + (size_t)(n0 + row) * KTOT + k0 + vc);
            Bs[vc + 0][row] = bv.x; Bs[vc + 1][row] = bv.y;
            Bs[vc + 2][row] = bv.z; Bs[vc + 3][row] = bv.w;
        }
        __syncthreads();

        #pragma unroll
        for (int kk = 0; kk < 16; kk++) {
            const float a = As[kk][r];
            #pragma unroll
            for (int j = 0; j < 8; j++)
                acc[j] = fmaf(a, Bs[kk][c0 + j], acc[j]);
        }
        __syncthreads();
    }

    const int crow = m0 + r;
    if (crow < nflag) {
        const size_t ro = (size_t)crow * HID + n0 + c0;
        #pragma unroll
        for (int j = 0; j < 8; j++)
            out[ro + j] = gelu_exact(acc[j] + bias[n0 + c0 + j]);
    }
}

// ------- main top-k from precomputed mma logits + tier-1 flagging ---------
__global__ __launch_bounds__(64)
void topk_from_logits(const float* __restrict__ logits, float* __restrict__ probs)
{
    __shared__ float lg[64][65];
    __shared__ float pv[64][2];
    __shared__ int   pi[64][2];

    const int n0 = blockIdx.x * 64;
    const int s  = threadIdx.x;

    #pragma unroll 8
    for (int r = 0; r < 64; r++)
        lg[r][s] = logits[(size_t)(n0 + r) * LPAD + s];
    __syncthreads();

    {
        float v1 = -3.4e38f, v2 = -3.4e38f, v3 = -3.4e38f;
        int   i1 = -1,       i2 = -1;
        #pragma unroll
        for (int j = 0; j < NS; j++) {
            float v = lg[s][j];
            if (v > v1)      { v3 = v2; v2 = v1; i2 = i1; v1 = v; i1 = j; }
            else if (v > v2) { v3 = v2; v2 = v;  i2 = j; }
            else if (v > v3) { v3 = v; }
        }
        const float e2  = expf(v2 - v1);
        const float inv = 1.0f / (1.0f + e2);
        pv[s][0] = inv;  pv[s][1] = e2 * inv;
        pi[s][0] = i1;   pi[s][1] = i2;
        if (v2 - v3 < TAU1) {
            int pos = atomicAdd(&g_nflag, 1);
            g_flagidx[pos] = n0 + s;
        }
    }
    __syncthreads();

    #pragma unroll 8
    for (int r = 0; r < 64; r++) {
        float p = 0.0f;
        if (s == pi[r][0])      p = pv[r][0];
        else if (s == pi[r][1]) p = pv[r][1];
        probs[(size_t)(n0 + r) * NS + s] = p;
    }
}

// ----------------------- replay logits kernels (exact fp32) ---------------
#define TTOK 8

template<int MODE>
__global__ __launch_bounds__(NS)
void logits_topk_kernel(const float* __restrict__ h,
                        const float* __restrict__ W2,
                        const float* __restrict__ b2,
                        float* __restrict__ probs)
{
    __shared__ float hs[TTOK][HID];
    __shared__ float lg[TTOK][NS];
    __shared__ float pv[TTOK][2];
    __shared__ int   pi[TTOK][2];

    const int n0 = blockIdx.x * TTOK;
    const int cnt = (MODE == 1) ? g_nflag : g_nflag2;
    if (n0 >= cnt) return;
    const int s  = threadIdx.x;

    {
        const float4* src = reinterpret_cast<const float4*>(h + (size_t)n0 * HID);
        float4* dst = reinterpret_cast<float4*>(&hs[0][0]);
        #pragma unroll
        for (int i = s; i < TTOK * HID / 4; i += NS) dst[i] = src[i];
    }
    __syncthreads();

    float acc[TTOK];
    #pragma unroll
    for (int tk = 0; tk < TTOK; tk++) acc[tk] = 0.0f;
    const float* w = W2 + (size_t)s * HID;
    for (int k = 0; k < HID; k += 4) {
        float4 wv = *reinterpret_cast<const float4*>(w + k);
        #pragma unroll
        for (int tk = 0; tk < TTOK; tk++) {
            acc[tk] = fmaf(wv.x, hs[tk][k + 0], acc[tk]);
            acc[tk] = fmaf(wv.y, hs[tk][k + 1], acc[tk]);
            acc[tk] = fmaf(wv.z, hs[tk][k + 2], acc[tk]);
            acc[tk] = fmaf(wv.w, hs[tk][k + 3], acc[tk]);
        }
    }
    const float bb = b2[s];
    #pragma unroll
    for (int tk = 0; tk < TTOK; tk++) lg[tk][s] = acc[tk] + bb;
    __syncthreads();

    if (s < TTOK && n0 + s < cnt) {
        float v1 = -3.4e38f, v2 = -3.4e38f, v3 = -3.4e38f;
        int   i1 = -1,       i2 = -1;
        #pragma unroll
        for (int j = 0; j < NS; j++) {
            float v = lg[s][j];
            if (v > v1)      { v3 = v2; v2 = v1; i2 = i1; v1 = v; i1 = j; }
            else if (v > v2) { v3 = v2; v2 = v;  i2 = j; }
            else if (v > v3) { v3 = v; }
        }
        const float e2  = expf(v2 - v1);
        const float inv = 1.0f / (1.0f + e2);
        pv[s][0] = inv;  pv[s][1] = e2 * inv;
        pi[s][0] = i1;   pi[s][1] = i2;
        if (MODE == 1 && (v2 - v3 < TAU2)) {
            int pos = atomicAdd(&g_nflag2, 1);
            g_flagidx2[pos] = g_flagidx[n0 + s];
        }
    }
    __syncthreads();

    #pragma unroll
    for (int tk = 0; tk < TTOK; tk++) {
        if (n0 + tk >= cnt) continue;
        float p = 0.0f;
        if (s == pi[tk][0])      p = pv[tk][0];
        else if (s == pi[tk][1]) p = pv[tk][1];
        const size_t row = (MODE == 1) ? (size_t)g_flagidx[n0 + tk]
                                       : (size_t)g_flagidx2[n0 + tk];
        probs[row * NS + s] = p;
    }
}

// ------------------------------ beta (fp16 hd) -----------------------------
__global__ __launch_bounds__(128)
void beta_kernel(const __half* __restrict__ hd, const float* __restrict__ Wd2,
                 const float* __restrict__ bd2, float* __restrict__ beta)
{
    const int warp = threadIdx.x >> 5;
    const int lane = threadIdx.x & 31;
    const int n = blockIdx.x * 4 + warp;
    const __half* row = hd + (size_t)n * (HID / 2);
    float acc = 0.0f;
    #pragma unroll
    for (int k = lane * 4; k < HID / 2; k += 128) {
        __half2 a01 = *reinterpret_cast<const __half2*>(row + k);
        __half2 a23 = *reinterpret_cast<const __half2*>(row + k + 2);
        float4 w = *reinterpret_cast<const float4*>(Wd2 + k);
        float2 f01 = __half22float2(a01);
        float2 f23 = __half22float2(a23);
        acc += f01.x * w.x + f01.y * w.y + f23.x * w.z + f23.y * w.w;
    }
    #pragma unroll
    for (int o = 16; o > 0; o >>= 1) acc += __shfl_xor_sync(0xffffffffu, acc, o);
    if (lane == 0) beta[n] = 1.0f / (1.0f + expf(-(acc + bd2[0])));
}

// ---------------------------------------------------------------------------
extern "C" void kernel_launch(void* const* d_in, const int* in_sizes, int n_in,
                              void* d_out, int out_size)
{
    const float* sm  = (const float*)d_in[0];
    const float* tm  = (const float*)d_in[1];
    const float* dg  = (const float*)d_in[2];
    const float* W1  = (const float*)d_in[3];
    const float* b1  = (const float*)d_in[4];
    const float* W2  = (const float*)d_in[5];
    const float* b2  = (const float*)d_in[6];
    const float* Wd1 = (const float*)d_in[7];
    const float* bd1 = (const float*)d_in[8];
    const float* Wd2 = (const float*)d_in[9];
    const float* bd2 = (const float*)d_in[10];

    float* out   = (float*)d_out;
    float* probs = out;
    float* beta  = out + (size_t)NTOK * NS;

    float *zptr, *hrep, *hrep2, *logit, *b2p;
    __half *hd16, *xh, *xl, *w1a, *w1b, *wdh, *w2h, *h16;
    cudaGetSymbolAddress((void**)&zptr,  g_z);
    cudaGetSymbolAddress((void**)&hd16,  g_hd16);
    cudaGetSymbolAddress((void**)&hrep,  g_hrep);
    cudaGetSymbolAddress((void**)&hrep2, g_hrep2);
    cudaGetSymbolAddress((void**)&logit, g_logits);
    cudaGetSymbolAddress((void**)&b2p,   g_b2p);
    cudaGetSymbolAddress((void**)&xh,  g_xh);
    cudaGetSymbolAddress((void**)&xl,  g_xl);
    cudaGetSymbolAddress((void**)&w1a, g_w1a);
    cudaGetSymbolAddress((void**)&w1b, g_w1b);
    cudaGetSymbolAddress((void**)&wdh, g_wd);
    cudaGetSymbolAddress((void**)&w2h, g_w2h);
    cudaGetSymbolAddress((void**)&h16, g_h16);

    cudaFuncSetAttribute((const void*)gemm_f16x1<KTOT, 0>,
                         cudaFuncAttributeMaxDynamicSharedMemorySize, SMEM_MMA_BYTES);
    cudaFuncSetAttribute((const void*)gemm_f16x1<HID, 1>,
                         cudaFuncAttributeMaxDynamicSharedMemorySize, SMEM_MMA_BYTES);
    cudaFuncSetAttribute((const void*)gemm_t1_delta,
                         cudaFuncAttributeMaxDynamicSharedMemorySize, T1_SMEM_BYTES);

    {
        const int nblkX = (3 * NTOK * HID / 4 + 255) / 256;
        splitX2h_all<<<nblkX, 256>>>(sm, tm, dg, xh, xl);
        int n4 = HID * KTOT / 4;
        splitW2h<<<(n4 + 255) / 256, 256>>>(W1, w1a, w1b, n4);
        n4 = (HID / 2) * KTOT / 4;
        convWh<<<(n4 + 255) / 256, 256>>>(Wd1, wdh, n4);
        prepW2<<<(LPAD * HID + 255) / 256, 256>>>(W2, b2, w2h, b2p);
    }

    // main merged GEMM1 + GEMMd (h -> h16 + z fp32; hd -> fp16)
    {
        dim3 grid(HID / 128 + (HID / 2) / 128, NTOK / 128);   // (12, 256)
        gemm_f16x1<KTOT, 0><<<grid, 256, SMEM_MMA_BYTES>>>(
            xh, w1a, wdh, b1, bd1, nullptr, hd16, h16, zptr,
            HID / 128, HID, HID / 2);
    }

    // logits = h16 @ W2h^T (+b2p), fp32 out [NTOK, 128]
    {
        dim3 grid(1, NTOK / 128);
        gemm_f16x1<HID, 1><<<grid, 256, SMEM_MMA_BYTES>>>(
            h16, w2h, w2h, b2p, b2p, logit, nullptr, nullptr, nullptr,
            1, LPAD, LPAD);
    }

    // top-2 + softmax + tier-1 flagging
    topk_from_logits<<<NTOK / 64, 64>>>(logit, probs);

    // tier-1: gathered 2-term DELTA mma repair + exact fp32 replay
    {
        dim3 g1(HID / 128, NTOK / 128);
        gemm_t1_delta<<<g1, 256, T1_SMEM_BYTES>>>(xh, xl, w1a, w1b, zptr, hrep);
        logits_topk_kernel<1><<<NTOK / TTOK, NS>>>(hrep, W2, b2, probs);
    }

    // tier-2: exact round-1 scalar replay
    {
        dim3 gr(HID / 128, NTOK / RBM);
        gemm_repair<<<gr, 256>>>(sm, tm, dg, W1, b1, hrep2);
        logits_topk_kernel<2><<<NTOK / TTOK, NS>>>(hrep2, W2, b2, probs);
    }

    beta_kernel<<<NTOK / 4, 128>>>(hd16, Wd2, bd2, beta);
}

// round 17
// speedup vs baseline: 1.1047x; 1.0015x over previous
#include <cuda_runtime.h>
#include <cuda_fp16.h>
#include <math.h>
#include <stdint.h>

#define NTOK 32768
#define HID  1024
#define NS   64
#define KTOT 3072
#define LPAD 128
#define TAU1 3e-3f
#define TAU2 2e-5f

// ------------------------- device scratch ---------------------------------
__device__ float g_z  [(size_t)NTOK * HID];      // pre-GELU h accumulator (+b1)
__device__ __half g_hd16[(size_t)NTOK * (HID / 2)];
__device__ float g_hrep [(size_t)NTOK * HID];
__device__ float g_hrep2[(size_t)NTOK * HID];
__device__ __half g_h16[(size_t)NTOK * HID];
__device__ __half g_xh[(size_t)NTOK * KTOT];
__device__ __half g_xl[(size_t)NTOK * KTOT];
__device__ __half g_w1a[(size_t)HID * KTOT];
__device__ __half g_w1b[(size_t)HID * KTOT];
__device__ __half g_wd[(size_t)(HID / 2) * KTOT];
__device__ __half g_w2h[(size_t)LPAD * HID];
__device__ float  g_b2p[LPAD];
__device__ int g_nflag;
__device__ int g_flagidx[NTOK];
__device__ int g_nflag2;
__device__ int g_flagidx2[NTOK];

__device__ __forceinline__ float gelu_exact(float x) {
    return 0.5f * x * (1.0f + erff(x * 0.70710678118654752440f));
}
__device__ __forceinline__ void cp16(uint32_t d, const void* s) {
    asm volatile("cp.async.cg.shared.global [%0], [%1], 16;" :: "r"(d), "l"(s));
}
#define CP_COMMIT() asm volatile("cp.async.commit_group;" ::: "memory")
#define CP_WAIT1()  asm volatile("cp.async.wait_group 1;" ::: "memory")
#define CP_WAIT2()  asm volatile("cp.async.wait_group 2;" ::: "memory")
__device__ __forceinline__ void mma16h(float* c, const uint32_t* a, const uint32_t* b) {
    asm volatile("mma.sync.aligned.m16n8k16.row.col.f32.f16.f16.f32 "
        "{%0,%1,%2,%3}, {%4,%5,%6,%7}, {%8,%9}, {%0,%1,%2,%3};"
        : "+f"(c[0]), "+f"(c[1]), "+f"(c[2]), "+f"(c[3])
        : "r"(a[0]), "r"(a[1]), "r"(a[2]), "r"(a[3]), "r"(b[0]), "r"(b[1]));
}
__device__ __forceinline__ void ldsm4(uint32_t& r0, uint32_t& r1, uint32_t& r2,
                                      uint32_t& r3, uint32_t addr) {
    asm volatile("ldmatrix.sync.aligned.m8n8.x4.shared.b16 {%0,%1,%2,%3}, [%4];"
                 : "=r"(r0), "=r"(r1), "=r"(r2), "=r"(r3) : "r"(addr));
}

// top-3 insert with jax tie-break (lowest index wins on equal value)
__device__ __forceinline__ void ins3(float* v, int* ix, float nv, int nidx) {
    bool g0 = (nv > v[0]) || (nv == v[0] && nidx < ix[0]);
    bool g1 = (nv > v[1]) || (nv == v[1] && nidx < ix[1]);
    bool g2 = (nv > v[2]) || (nv == v[2] && nidx < ix[2]);
    if (g0) { v[2] = v[1]; ix[2] = ix[1]; v[1] = v[0]; ix[1] = ix[0]; v[0] = nv; ix[0] = nidx; }
    else if (g1) { v[2] = v[1]; ix[2] = ix[1]; v[1] = nv; ix[1] = nidx; }
    else if (g2) { v[2] = nv; ix[2] = nidx; }
}

// ---------------------- prep kernels --------------------------------------
__device__ __forceinline__ void hsplit2(float x, uint16_t& s1, uint16_t& s2) {
    __half h1 = __float2half_rn(x);
    __half h2 = __float2half_rn(x - __half2float(h1));
    s1 = __half_as_ushort(h1);
    s2 = __half_as_ushort(h2);
}

__global__ __launch_bounds__(256)
void splitX2h_all(const float* __restrict__ x0, const float* __restrict__ x1,
                  const float* __restrict__ x2,
                  __half* __restrict__ oa, __half* __restrict__ ob)
{
    const int gid = blockIdx.x * 256 + threadIdx.x;
    if (gid >= 3 * NTOK * HID / 4) return;
    const int part = gid / (NTOK * HID / 4);
    const int idx4 = gid - part * (NTOK * HID / 4);
    const float* in = (part == 0) ? x0 : ((part == 1) ? x1 : x2);
    const int n = idx4 >> 8, c4 = idx4 & 255;
    float4 v = reinterpret_cast<const float4*>(in)[idx4];
    uint16_t a[4], b[4];
    hsplit2(v.x, a[0], b[0]); hsplit2(v.y, a[1], b[1]);
    hsplit2(v.z, a[2], b[2]); hsplit2(v.w, a[3], b[3]);
    const size_t off = (size_t)n * KTOT + part * HID + c4 * 4;
    *reinterpret_cast<uint2*>(oa + off) =
        make_uint2((uint32_t)a[0] | ((uint32_t)a[1] << 16),
                   (uint32_t)a[2] | ((uint32_t)a[3] << 16));
    *reinterpret_cast<uint2*>(ob + off) =
        make_uint2((uint32_t)b[0] | ((uint32_t)b[1] << 16),
                   (uint32_t)b[2] | ((uint32_t)b[3] << 16));
}

// fused W prep: W1 split (region A), Wd1 conv (region B), W2 pad (region C), flags
#define W1N4 (HID * KTOT / 4)
#define WDN4 ((HID / 2) * KTOT / 4)
#define W2N4 (LPAD * HID / 4)

__global__ __launch_bounds__(256)
void prepW_all(const float* __restrict__ W1,
               const float* __restrict__ Wd1,
               const float* __restrict__ W2, const float* __restrict__ b2,
               __half* __restrict__ w1a, __half* __restrict__ w1b,
               __half* __restrict__ wdh,
               __half* __restrict__ w2h, float* __restrict__ b2p)
{
    const int gid = blockIdx.x * 256 + threadIdx.x;
    if (gid == 0) { g_nflag = 0; g_nflag2 = 0; }
    if (gid < LPAD) b2p[gid] = (gid < NS) ? b2[gid] : 0.0f;

    if (gid < W1N4) {
        float4 v = reinterpret_cast<const float4*>(W1)[gid];
        uint16_t a[4], b[4];
        hsplit2(v.x, a[0], b[0]); hsplit2(v.y, a[1], b[1]);
        hsplit2(v.z, a[2], b[2]); hsplit2(v.w, a[3], b[3]);
        const size_t off = (size_t)gid * 4;
        *reinterpret_cast<uint2*>(w1a + off) =
            make_uint2((uint32_t)a[0] | ((uint32_t)a[1] << 16),
                       (uint32_t)a[2] | ((uint32_t)a[3] << 16));
        *reinterpret_cast<uint2*>(w1b + off) =
            make_uint2((uint32_t)b[0] | ((uint32_t)b[1] << 16),
                       (uint32_t)b[2] | ((uint32_t)b[3] << 16));
    } else if (gid < W1N4 + WDN4) {
        const int i = gid - W1N4;
        float4 v = reinterpret_cast<const float4*>(Wd1)[i];
        uint16_t a0 = __half_as_ushort(__float2half_rn(v.x));
        uint16_t a1 = __half_as_ushort(__float2half_rn(v.y));
        uint16_t a2 = __half_as_ushort(__float2half_rn(v.z));
        uint16_t a3 = __half_as_ushort(__float2half_rn(v.w));
        *reinterpret_cast<uint2*>(wdh + (size_t)i * 4) =
            make_uint2((uint32_t)a0 | ((uint32_t)a1 << 16),
                       (uint32_t)a2 | ((uint32_t)a3 << 16));
    } else if (gid < W1N4 + WDN4 + W2N4) {
        const int i = gid - W1N4 - WDN4;           // over LPAD*HID/4
        const int row = (i * 4) >> 10;
        uint16_t a[4];
        if (row < NS) {
            float4 v = reinterpret_cast<const float4*>(W2)[((size_t)row * HID + ((i * 4) & 1023)) / 4];
            a[0] = __half_as_ushort(__float2half_rn(v.x));
            a[1] = __half_as_ushort(__float2half_rn(v.y));
            a[2] = __half_as_ushort(__float2half_rn(v.z));
            a[3] = __half_as_ushort(__float2half_rn(v.w));
        } else {
            a[0] = a[1] = a[2] = a[3] = 0;
        }
        *reinterpret_cast<uint2*>(w2h + (size_t)i * 4) =
            make_uint2((uint32_t)a[0] | ((uint32_t)a[1] << 16),
                       (uint32_t)a[2] | ((uint32_t)a[3] << 16));
    }
}

// ---- MAIN fp16 1-term mma GEMM, ldmatrix, 3-stage (proven skeleton) ------
// OUTMODE 0: h-part -> h16 + z (pre-GELU fp32); hd-part -> fp16 hd + GELU
// OUTMODE 1: FUSED logits epilogue -> probs + tier-1 flags
#define RSW   20
#define LVLW  (128 * RSW)
#define NITER (KTOT / 32)
#define NSTAGE 3
#define SWORDS (2 * LVLW)
#define SMEM_MMA_BYTES (NSTAGE * SWORDS * 4)   // 61440

static __device__ __forceinline__ void fill_stage2(
    const __half* __restrict__ xh, const __half* __restrict__ w,
    int m0, int n0, int k0, int tid, int stage, uint32_t sbase, int kstride)
{
    #pragma unroll
    for (int p = 0; p < 4; p++) {
        const int slot = p >> 1;
        const int c    = tid + (p & 1) * 256;
        const int row  = c >> 2;
        const int q    = c & 3;
        const __half* src = (slot == 0)
            ? xh + (size_t)(m0 + row) * kstride + k0 + q * 8
            : w  + (size_t)(n0 + row) * kstride + k0 + q * 8;
        const uint32_t dw = (uint32_t)(stage * SWORDS + slot * LVLW + row * RSW + q * 4);
        cp16(sbase + dw * 4u, src);
    }
}

template<int KDIM, int OUTMODE>
__global__ void __launch_bounds__(256)
gemm_f16x1(const __half* __restrict__ xh,
           const __half* __restrict__ w1, const __half* __restrict__ wd,
           const float* __restrict__ b1, const float* __restrict__ bd,
           float* __restrict__ probs, __half* __restrict__ outd16,
           __half* __restrict__ h16, float* __restrict__ zout,
           int nblk1, int nout1, int nout2)
{
    extern __shared__ uint32_t smw[];
    const int bx = blockIdx.x;
    const bool first = (bx < nblk1);
    const __half* w    = first ? w1 : wd;
    const float* bias  = first ? b1 : bd;
    const int Nout     = first ? nout1 : nout2;
    const int n0       = (first ? bx : bx - nblk1) * 128;

    const int tid  = threadIdx.x;
    const int lane = tid & 31;
    const int wid  = tid >> 5;
    const int g    = lane >> 2;
    const int t    = lane & 3;
    const int warp_m = wid >> 1;
    const int warp_n = wid & 1;
    const int m0 = blockIdx.y * 128;
    const uint32_t sbase = (uint32_t)__cvta_generic_to_shared(smw);

    const int la_row  = (lane & 7) + ((lane >> 3) & 1) * 8;
    const int la_colw = ((lane >> 4) & 1) * 4;
    const int lb_row  = (lane & 7) + ((lane >> 4) & 1) * 8;
    const int lb_colw = ((lane >> 3) & 1) * 4;
    const uint32_t aw0 = (uint32_t)((warp_m * 32 + la_row) * RSW + la_colw);
    const uint32_t bw0 = (uint32_t)(LVLW + (warp_n * 64 + lb_row) * RSW + lb_colw);

    float acc[2][8][4];
    #pragma unroll
    for (int mi = 0; mi < 2; mi++)
        #pragma unroll
        for (int ni = 0; ni < 8; ni++)
            #pragma unroll
            for (int q = 0; q < 4; q++) acc[mi][ni][q] = 0.0f;

    const int niter = KDIM / 32;
    fill_stage2(xh, w, m0, n0, 0,  tid, 0, sbase, KDIM); CP_COMMIT();
    fill_stage2(xh, w, m0, n0, 32, tid, 1, sbase, KDIM); CP_COMMIT();
    fill_stage2(xh, w, m0, n0, 64, tid, 2, sbase, KDIM); CP_COMMIT();

    int stage = 0;
    #pragma unroll 1
    for (int iter = 0; iter < niter; iter++) {
        CP_WAIT2();
        __syncthreads();
        const uint32_t sstage = sbase + (uint32_t)(stage * SWORDS) * 4u;

        #pragma unroll
        for (int kc = 0; kc < 2; kc++) {
            uint32_t af[2][4];
            #pragma unroll
            for (int mi = 0; mi < 2; mi++)
                ldsm4(af[mi][0], af[mi][1], af[mi][2], af[mi][3],
                      sstage + (aw0 + (uint32_t)(mi * 16 * RSW + kc * 8)) * 4u);

            uint32_t bf_[8][2];
            #pragma unroll
            for (int p = 0; p < 4; p++) {
                uint32_t r0, r1, r2, r3;
                ldsm4(r0, r1, r2, r3,
                      sstage + (bw0 + (uint32_t)(p * 16 * RSW + kc * 8)) * 4u);
                bf_[2 * p][0]     = r0;  bf_[2 * p][1]     = r1;
                bf_[2 * p + 1][0] = r2;  bf_[2 * p + 1][1] = r3;
            }

            #pragma unroll
            for (int mi = 0; mi < 2; mi++)
                #pragma unroll
                for (int ni = 0; ni < 8; ni++)
                    mma16h(acc[mi][ni], af[mi], bf_[ni]);
        }
        __syncthreads();
        if (iter + NSTAGE < niter)
            fill_stage2(xh, w, m0, n0, (iter + NSTAGE) * 32, tid, stage, sbase, KDIM);
        CP_COMMIT();
        stage = (stage == NSTAGE - 1) ? 0 : stage + 1;
    }

    if (OUTMODE == 0) {
        #pragma unroll
        for (int mi = 0; mi < 2; mi++)
            #pragma unroll
            for (int half = 0; half < 2; half++) {
                const int row = m0 + warp_m * 32 + mi * 16 + g + half * 8;
                #pragma unroll
                for (int ni = 0; ni < 8; ni++) {
                    const int col = n0 + warp_n * 64 + ni * 8 + 2 * t;
                    float2 b = *(const float2*)(bias + col);
                    float2 z;
                    z.x = acc[mi][ni][half * 2 + 0] + b.x;
                    z.y = acc[mi][ni][half * 2 + 1] + b.y;
                    float2 r;
                    r.x = gelu_exact(z.x);
                    r.y = gelu_exact(z.y);
                    if (first) {
                        *(__half2*)(h16 + (size_t)row * HID + col) =
                            __floats2half2_rn(r.x, r.y);
                        *(float2*)(zout + (size_t)row * HID + col) = z;
                    } else {
                        *(__half2*)(outd16 + (size_t)row * Nout + col) =
                            __floats2half2_rn(r.x, r.y);
                    }
                }
            }
    } else {
        // FUSED logits top-k epilogue. Real columns (0..63) live in warp_n==0.
        if (warp_n == 0) {
            float bcol[8][2];
            #pragma unroll
            for (int ni = 0; ni < 8; ni++) {
                float2 b = *(const float2*)(bias + ni * 8 + 2 * t);
                bcol[ni][0] = b.x; bcol[ni][1] = b.y;
            }
            #pragma unroll
            for (int mi = 0; mi < 2; mi++)
                #pragma unroll
                for (int half = 0; half < 2; half++) {
                    const int row = m0 + warp_m * 32 + mi * 16 + g + half * 8;
                    float lv[16];
                    float v[3] = {-3.4e38f, -3.4e38f, -3.4e38f};
                    int   ix[3] = {1 << 30, 1 << 30, 1 << 30};
                    #pragma unroll
                    for (int ni = 0; ni < 8; ni++) {
                        lv[2 * ni]     = acc[mi][ni][half * 2 + 0] + bcol[ni][0];
                        lv[2 * ni + 1] = acc[mi][ni][half * 2 + 1] + bcol[ni][1];
                        ins3(v, ix, lv[2 * ni],     ni * 8 + 2 * t);
                        ins3(v, ix, lv[2 * ni + 1], ni * 8 + 2 * t + 1);
                    }
                    // merge across the 4-lane quad (lanes differ in bits 0-1)
                    #pragma unroll
                    for (int off = 1; off <= 2; off <<= 1) {
                        float ov[3]; int oi[3];
                        #pragma unroll
                        for (int e = 0; e < 3; e++) {
                            ov[e] = __shfl_xor_sync(0xffffffffu, v[e], off);
                            oi[e] = __shfl_xor_sync(0xffffffffu, ix[e], off);
                        }
                        #pragma unroll
                        for (int e = 0; e < 3; e++) ins3(v, ix, ov[e], oi[e]);
                    }
                    const float e2  = expf(v[1] - v[0]);
                    const float inv = 1.0f / (1.0f + e2);
                    const float p1 = inv, p2 = e2 * inv;
                    if (t == 0 && (v[1] - v[2] < TAU1)) {
                        int pos = atomicAdd(&g_nflag, 1);
                        g_flagidx[pos] = row;
                    }
                    #pragma unroll
                    for (int ni = 0; ni < 8; ni++) {
                        const int col = ni * 8 + 2 * t;
                        float2 pr;
                        pr.x = (col == ix[0]) ? p1 : ((col == ix[1]) ? p2 : 0.0f);
                        pr.y = (col + 1 == ix[0]) ? p1 : ((col + 1 == ix[1]) ? p2 : 0.0f);
                        *(float2*)(probs + (size_t)row * NS + col) = pr;
                    }
                }
        }
    }
}

// ---- TIER-1 repair: gathered 2-term DELTA mma GEMM (+ z cache) -----------
#define T1_SWORDS (4 * LVLW)
#define T1_SMEM_BYTES (2 * T1_SWORDS * 4)   // 81920

static __device__ __forceinline__ void fill_t1(
    const __half* __restrict__ xa, const __half* __restrict__ xb,
    const __half* __restrict__ wa, const __half* __restrict__ wb,
    const int* sidx, int n0, int k0, int tid, int stage, uint32_t sbase)
{
    const __half* srcs[4] = {xa, xb, wa, wb};
    #pragma unroll
    for (int p = 0; p < 8; p++) {
        const int slot = p >> 1;
        const int c    = tid + (p & 1) * 256;
        const int row  = c >> 2;
        const int q    = c & 3;
        const __half* src = (slot < 2)
            ? srcs[slot] + (size_t)sidx[row] * KTOT + k0 + q * 8
            : srcs[slot] + (size_t)(n0 + row) * KTOT + k0 + q * 8;
        const uint32_t dw = (uint32_t)(stage * T1_SWORDS + slot * LVLW + row * RSW + q * 4);
        cp16(sbase + dw * 4u, src);
    }
}

__global__ void __launch_bounds__(256)
gemm_t1_delta(const __half* __restrict__ xa, const __half* __restrict__ xb,
              const __half* __restrict__ wa, const __half* __restrict__ wb,
              const float* __restrict__ z, float* __restrict__ out)
{
    const int nflag = g_nflag;
    const int m0 = blockIdx.y * 128;
    if (m0 >= nflag) return;
    extern __shared__ uint32_t smw[];
    __shared__ int sidx[128];

    const int tid  = threadIdx.x;
    const int lane = tid & 31;
    const int wid  = tid >> 5;
    const int g    = lane >> 2;
    const int t    = lane & 3;
    const int warp_m = wid >> 1;
    const int warp_n = wid & 1;
    const int n0 = blockIdx.x * 128;
    const uint32_t sbase = (uint32_t)__cvta_generic_to_shared(smw);

    if (tid < 128)
        sidx[tid] = g_flagidx[(m0 + tid < nflag) ? m0 + tid : 0];
    __syncthreads();

    const int la_row  = (lane & 7) + ((lane >> 3) & 1) * 8;
    const int la_colw = ((lane >> 4) & 1) * 4;
    const int lb_row  = (lane & 7) + ((lane >> 4) & 1) * 8;
    const int lb_colw = ((lane >> 3) & 1) * 4;
    const uint32_t aw0 = (uint32_t)((warp_m * 32 + la_row) * RSW + la_colw);
    const uint32_t bw0 = (uint32_t)(2 * LVLW + (warp_n * 64 + lb_row) * RSW + lb_colw);

    float acc[2][8][4];
    #pragma unroll
    for (int mi = 0; mi < 2; mi++)
        #pragma unroll
        for (int ni = 0; ni < 8; ni++)
            #pragma unroll
            for (int q = 0; q < 4; q++) acc[mi][ni][q] = 0.0f;

    fill_t1(xa, xb, wa, wb, sidx, n0, 0,  tid, 0, sbase); CP_COMMIT();
    fill_t1(xa, xb, wa, wb, sidx, n0, 32, tid, 1, sbase); CP_COMMIT();

    #pragma unroll 1
    for (int iter = 0; iter < NITER; iter++) {
        CP_WAIT1();
        __syncthreads();
        const int stage = iter & 1;
        const uint32_t sstage = sbase + (uint32_t)(stage * T1_SWORDS) * 4u;

        #pragma unroll
        for (int kc = 0; kc < 2; kc++) {
            uint32_t af[2][2][4];
            #pragma unroll
            for (int l = 0; l < 2; l++)
                #pragma unroll
                for (int mi = 0; mi < 2; mi++)
                    ldsm4(af[l][mi][0], af[l][mi][1], af[l][mi][2], af[l][mi][3],
                          sstage + (aw0 + (uint32_t)(l * LVLW + mi * 16 * RSW + kc * 8)) * 4u);

            uint32_t bf_[2][8][2];
            #pragma unroll
            for (int l = 0; l < 2; l++)
                #pragma unroll
                for (int p = 0; p < 4; p++) {
                    uint32_t r0, r1, r2, r3;
                    ldsm4(r0, r1, r2, r3,
                          sstage + (bw0 + (uint32_t)(l * LVLW + p * 16 * RSW + kc * 8)) * 4u);
                    bf_[l][2 * p][0]     = r0;  bf_[l][2 * p][1]     = r1;
                    bf_[l][2 * p + 1][0] = r2;  bf_[l][2 * p + 1][1] = r3;
                }

            #pragma unroll
            for (int mi = 0; mi < 2; mi++)
                #pragma unroll
                for (int ni = 0; ni < 8; ni++)
                    mma16h(acc[mi][ni], af[0][mi], bf_[1][ni]);
            #pragma unroll
            for (int mi = 0; mi < 2; mi++)
                #pragma unroll
                for (int ni = 0; ni < 8; ni++)
                    mma16h(acc[mi][ni], af[1][mi], bf_[0][ni]);
        }
        __syncthreads();
        if (iter + 2 < NITER)
            fill_t1(xa, xb, wa, wb, sidx, n0, (iter + 2) * 32, tid, stage, sbase);
        CP_COMMIT();
    }

    #pragma unroll
    for (int mi = 0; mi < 2; mi++)
        #pragma unroll
        for (int half = 0; half < 2; half++) {
            const int crow = m0 + warp_m * 32 + mi * 16 + g + half * 8;
            if (crow < nflag) {
                const size_t zrow = (size_t)sidx[warp_m * 32 + mi * 16 + g + half * 8] * HID;
                #pragma unroll
                for (int ni = 0; ni < 8; ni++) {
                    const int col = n0 + warp_n * 64 + ni * 8 + 2 * t;
                    float2 zv = *(const float2*)(z + zrow + col);
                    float2 r;
                    r.x = gelu_exact(zv.x + acc[mi][ni][half * 2 + 0]);
                    r.y = gelu_exact(zv.y + acc[mi][ni][half * 2 + 1]);
                    *(float2*)(out + (size_t)crow * HID + col) = r;
                }
            }
        }
}

// ---- TIER-2 exact repair: round-1 fp32 fmaf chain, gathered --------------
#define RBM 16

__global__ __launch_bounds__(256)
void gemm_repair(const float* __restrict__ x0, const float* __restrict__ x1,
                 const float* __restrict__ x2, const float* __restrict__ W,
                 const float* __restrict__ bias, float* __restrict__ out)
{
    const int nflag = g_nflag2;
    const int m0 = blockIdx.y * RBM;
    if (m0 >= nflag) return;
    __shared__ float As[16][RBM];
    __shared__ float Bs[16][128];

    const int tid = threadIdx.x;
    const int n0  = blockIdx.x * 128;
    const int r   = tid >> 4;
    const int c0  = (tid & 15) * 8;

    float acc[8];
    #pragma unroll
    for (int j = 0; j < 8; j++) acc[j] = 0.0f;

    for (int k0 = 0; k0 < KTOT; k0 += 16) {
        const int part = k0 / HID;
        const float* xp = (part == 0) ? x0 : ((part == 1) ? x1 : x2);
        const int kp = k0 - part * HID;

        {
            const int r2 = tid >> 4, kk = tid & 15;
            const int cr = (m0 + r2 < nflag) ? (m0 + r2) : 0;
            const int grow = g_flagidx2[cr];
            As[kk][r2] = xp[(size_t)grow * HID + kp + kk];
        }
        #pragma unroll
        for (int p = 0; p < 2; p++) {
            const int slot = tid + p * 256;
            const int row  = slot >> 2;
            const int vc   = (slot & 3) * 4;
            float4 bv = *reinterpret_cast<const float4*>(
                W + (size_t)(n0 + row) * KTOT + k0 + vc);
            Bs[vc + 0][row] = bv.x; Bs[vc + 1][row] = bv.y;
            Bs[vc + 2][row] = bv.z; Bs[vc + 3][row] = bv.w;
        }
        __syncthreads();

        #pragma unroll
        for (int kk = 0; kk < 16; kk++) {
            const float a = As[kk][r];
            #pragma unroll
            for (int j = 0; j < 8; j++)
                acc[j] = fmaf(a, Bs[kk][c0 + j], acc[j]);
        }
        __syncthreads();
    }

    const int crow = m0 + r;
    if (crow < nflag) {
        const size_t ro = (size_t)crow * HID + n0 + c0;
        #pragma unroll
        for (int j = 0; j < 8; j++)
            out[ro + j] = gelu_exact(acc[j] + bias[n0 + c0 + j]);
    }
}

// ----------------------- replay logits kernels (exact fp32) ---------------
#define TTOK 8

template<int MODE>
__global__ __launch_bounds__(NS)
void logits_topk_kernel(const float* __restrict__ h,
                        const float* __restrict__ W2,
                        const float* __restrict__ b2,
                        float* __restrict__ probs)
{
    __shared__ float hs[TTOK][HID];
    __shared__ float lg[TTOK][NS];
    __shared__ float pv[TTOK][2];
    __shared__ int   pi[TTOK][2];

    const int n0 = blockIdx.x * TTOK;
    const int cnt = (MODE == 1) ? g_nflag : g_nflag2;
    if (n0 >= cnt) return;
    const int s  = threadIdx.x;

    {
        const float4* src = reinterpret_cast<const float4*>(h + (size_t)n0 * HID);
        float4* dst = reinterpret_cast<float4*>(&hs[0][0]);
        #pragma unroll
        for (int i = s; i < TTOK * HID / 4; i += NS) dst[i] = src[i];
    }
    __syncthreads();

    float acc[TTOK];
    #pragma unroll
    for (int tk = 0; tk < TTOK; tk++) acc[tk] = 0.0f;
    const float* w = W2 + (size_t)s * HID;
    for (int k = 0; k < HID; k += 4) {
        float4 wv = *reinterpret_cast<const float4*>(w + k);
        #pragma unroll
        for (int tk = 0; tk < TTOK; tk++) {
            acc[tk] = fmaf(wv.x, hs[tk][k + 0], acc[tk]);
            acc[tk] = fmaf(wv.y, hs[tk][k + 1], acc[tk]);
            acc[tk] = fmaf(wv.z, hs[tk][k + 2], acc[tk]);
            acc[tk] = fmaf(wv.w, hs[tk][k + 3], acc[tk]);
        }
    }
    const float bb = b2[s];
    #pragma unroll
    for (int tk = 0; tk < TTOK; tk++) lg[tk][s] = acc[tk] + bb;
    __syncthreads();

    if (s < TTOK && n0 + s < cnt) {
        float v1 = -3.4e38f, v2 = -3.4e38f, v3 = -3.4e38f;
        int   i1 = -1,       i2 = -1;
        #pragma unroll
        for (int j = 0; j < NS; j++) {
            float v = lg[s][j];
            if (v > v1)      { v3 = v2; v2 = v1; i2 = i1; v1 = v; i1 = j; }
            else if (v > v2) { v3 = v2; v2 = v;  i2 = j; }
            else if (v > v3) { v3 = v; }
        }
        const float e2  = expf(v2 - v1);
        const float inv = 1.0f / (1.0f + e2);
        pv[s][0] = inv;  pv[s][1] = e2 * inv;
        pi[s][0] = i1;   pi[s][1] = i2;
        if (MODE == 1 && (v2 - v3 < TAU2)) {
            int pos = atomicAdd(&g_nflag2, 1);
            g_flagidx2[pos] = g_flagidx[n0 + s];
        }
    }
    __syncthreads();

    #pragma unroll
    for (int tk = 0; tk < TTOK; tk++) {
        if (n0 + tk >= cnt) continue;
        float p = 0.0f;
        if (s == pi[tk][0])      p = pv[tk][0];
        else if (s == pi[tk][1]) p = pv[tk][1];
        const size_t row = (MODE == 1) ? (size_t)g_flagidx[n0 + tk]
                                       : (size_t)g_flagidx2[n0 + tk];
        probs[row * NS + s] = p;
    }
}

// ------------------------------ beta (fp16 hd) -----------------------------
__global__ __launch_bounds__(128)
void beta_kernel(const __half* __restrict__ hd, const float* __restrict__ Wd2,
                 const float* __restrict__ bd2, float* __restrict__ beta)
{
    const int warp = threadIdx.x >> 5;
    const int lane = threadIdx.x & 31;
    const int n = blockIdx.x * 4 + warp;
    const __half* row = hd + (size_t)n * (HID / 2);
    float acc = 0.0f;
    #pragma unroll
    for (int k = lane * 4; k < HID / 2; k += 128) {
        __half2 a01 = *reinterpret_cast<const __half2*>(row + k);
        __half2 a23 = *reinterpret_cast<const __half2*>(row + k + 2);
        float4 w = *reinterpret_cast<const float4*>(Wd2 + k);
        float2 f01 = __half22float2(a01);
        float2 f23 = __half22float2(a23);
        acc += f01.x * w.x + f01.y * w.y + f23.x * w.z + f23.y * w.w;
    }
    #pragma unroll
    for (int o = 16; o > 0; o >>= 1) acc += __shfl_xor_sync(0xffffffffu, acc, o);
    if (lane == 0) beta[n] = 1.0f / (1.0f + expf(-(acc + bd2[0])));
}

// ---------------------------------------------------------------------------
extern "C" void kernel_launch(void* const* d_in, const int* in_sizes, int n_in,
                              void* d_out, int out_size)
{
    const float* sm  = (const float*)d_in[0];
    const float* tm  = (const float*)d_in[1];
    const float* dg  = (const float*)d_in[2];
    const float* W1  = (const float*)d_in[3];
    const float* b1  = (const float*)d_in[4];
    const float* W2  = (const float*)d_in[5];
    const float* b2  = (const float*)d_in[6];
    const float* Wd1 = (const float*)d_in[7];
    const float* bd1 = (const float*)d_in[8];
    const float* Wd2 = (const float*)d_in[9];
    const float* bd2 = (const float*)d_in[10];

    float* out   = (float*)d_out;
    float* probs = out;
    float* beta  = out + (size_t)NTOK * NS;

    float *zptr, *hrep, *hrep2, *b2p;
    __half *hd16, *xh, *xl, *w1a, *w1b, *wdh, *w2h, *h16;
    cudaGetSymbolAddress((void**)&zptr,  g_z);
    cudaGetSymbolAddress((void**)&hd16,  g_hd16);
    cudaGetSymbolAddress((void**)&hrep,  g_hrep);
    cudaGetSymbolAddress((void**)&hrep2, g_hrep2);
    cudaGetSymbolAddress((void**)&b2p,   g_b2p);
    cudaGetSymbolAddress((void**)&xh,  g_xh);
    cudaGetSymbolAddress((void**)&xl,  g_xl);
    cudaGetSymbolAddress((void**)&w1a, g_w1a);
    cudaGetSymbolAddress((void**)&w1b, g_w1b);
    cudaGetSymbolAddress((void**)&wdh, g_wd);
    cudaGetSymbolAddress((void**)&w2h, g_w2h);
    cudaGetSymbolAddress((void**)&h16, g_h16);

    cudaFuncSetAttribute((const void*)gemm_f16x1<KTOT, 0>,
                         cudaFuncAttributeMaxDynamicSharedMemorySize, SMEM_MMA_BYTES);
    cudaFuncSetAttribute((const void*)gemm_f16x1<HID, 1>,
                         cudaFuncAttributeMaxDynamicSharedMemorySize, SMEM_MMA_BYTES);
    cudaFuncSetAttribute((const void*)gemm_t1_delta,
                         cudaFuncAttributeMaxDynamicSharedMemorySize, T1_SMEM_BYTES);

    {
        const int nblkX = (3 * NTOK * HID / 4 + 255) / 256;
        splitX2h_all<<<nblkX, 256>>>(sm, tm, dg, xh, xl);
        const int nW = W1N4 + WDN4 + W2N4;
        prepW_all<<<(nW + 255) / 256, 256>>>(W1, Wd1, W2, b2,
                                             w1a, w1b, wdh, w2h, b2p);
    }

    // main merged GEMM1 + GEMMd (h -> h16 + z fp32; hd -> fp16)
    {
        dim3 grid(HID / 128 + (HID / 2) / 128, NTOK / 128);   // (12, 256)
        gemm_f16x1<KTOT, 0><<<grid, 256, SMEM_MMA_BYTES>>>(
            xh, w1a, wdh, b1, bd1, nullptr, hd16, h16, zptr,
            HID / 128, HID, HID / 2);
    }

    // logits GEMM with FUSED top-2/softmax/flagging epilogue -> probs
    {
        dim3 grid(1, NTOK / 128);
        gemm_f16x1<HID, 1><<<grid, 256, SMEM_MMA_BYTES>>>(
            h16, w2h, w2h, b2p, b2p, probs, nullptr, nullptr, nullptr,
            1, LPAD, LPAD);
    }

    // tier-1: gathered 2-term DELTA mma repair + exact fp32 replay
    {
        dim3 g1(HID / 128, NTOK / 128);
        gemm_t1_delta<<<g1, 256, T1_SMEM_BYTES>>>(xh, xl, w1a, w1b, zptr, hrep);
        logits_topk_kernel<1><<<NTOK / TTOK, NS>>>(hrep, W2, b2, probs);
    }

    // tier-2: exact round-1 scalar replay
    {
        dim3 gr(HID / 128, NTOK / RBM);
        gemm_repair<<<gr, 256>>>(sm, tm, dg, W1, b1, hrep2);
        logits_topk_kernel<2><<<NTOK / TTOK, NS>>>(hrep2, W2, b2, probs);
    }

    beta_kernel<<<NTOK / 4, 128>>>(hd16, Wd2, bd2, beta);
}